// round 11
// baseline (speedup 1.0000x reference)
#include <cuda_runtime.h>
#include <cuda_fp16.h>
#include <stdint.h>

// Problem constants
#define Bsz 8
#define Ssz 20
#define Fsz 200
#define Dsz 2048
#define Tn  20
#define En  128
#define Hn  128
#define CDn 300
#define THn 128
#define Mrows (Bsz*Ssz*Fsz)     // 32000
#define ROWS_PER_B (Ssz*Fsz)    // 4000

// Scratch (no allocations allowed)
__device__ float g_pool[Bsz*Dsz];
__device__ float g_venc[Bsz*Hn];                  // pooled@W_enc + concept terms
__device__ float g_vw3[Bsz*Hn];
__device__ float g_probs[Bsz*Tn];
__device__ float g_contrib[Tn*Hn];
__device__ __half g_Wh[Hn*Dsz];                   // W1^T fp16  [n][k]
__device__ float4 g_acc[250*4096];                // GEMM acc scratch (16 MB)

// ---------------------------------------------------------------------------
__device__ __forceinline__ uint32_t smem_u32(const void* p) {
    uint32_t a;
    asm("{ .reg .u64 t; cvta.to.shared.u64 t, %1; cvt.u32.u64 %0, t; }"
        : "=r"(a) : "l"(p));
    return a;
}
__device__ __forceinline__ void mma16816h(float* d, const uint32_t* a, const uint32_t* b) {
    asm volatile(
        "mma.sync.aligned.m16n8k16.row.col.f32.f16.f16.f32 "
        "{%0,%1,%2,%3}, {%4,%5,%6,%7}, {%8,%9}, {%0,%1,%2,%3};"
        : "+f"(d[0]), "+f"(d[1]), "+f"(d[2]), "+f"(d[3])
        : "r"(a[0]), "r"(a[1]), "r"(a[2]), "r"(a[3]), "r"(b[0]), "r"(b[1]));
}
#define LDSM4(r0, r1, r2, r3, addr) \
    asm volatile("ldmatrix.sync.aligned.m8n8.x4.shared.b16 {%0,%1,%2,%3}, [%4];" \
                 : "=r"(r0), "=r"(r1), "=r"(r2), "=r"(r3) : "r"(addr))
#define CP_ASYNC16(dst, src) \
    asm volatile("cp.async.cg.shared.global [%0], [%1], 16;" :: "r"(dst), "l"(src))
#define CP_COMMIT() asm volatile("cp.async.commit_group;")
#define CP_WAIT1()  asm volatile("cp.async.wait_group 1;")
#define CP_WAIT0()  asm volatile("cp.async.wait_group 0;")

__device__ __forceinline__ uint32_t packh2(__half a, __half b) {
    __half2 h = __halves2half2(a, b);
    return *(uint32_t*)&h;
}

// ---------------------------------------------------------------------------
// prep: contrib (0..19) + zero g_pool (20..83) + W1 transpose (84..115)
// + zero g_venc (116).  grid 117 x 256
// ---------------------------------------------------------------------------
__global__ void prep_kernel(const float* __restrict__ W1,
                            const float* __restrict__ topic_emb,
                            const float* __restrict__ W2) {
    int bx = blockIdx.x, tid = threadIdx.x;
    if (bx < Tn) {
        __shared__ float red[2][Hn];
        int h = tid & 127, e2 = tid >> 7;
        float acc = 0.f;
        int e0 = e2 * 64;
        #pragma unroll 8
        for (int e = e0; e < e0 + 64; e++)
            acc += topic_emb[bx * En + e] * W2[e * Hn + h];
        red[e2][h] = acc;
        __syncthreads();
        if (e2 == 0) g_contrib[bx * Hn + h] = red[0][h] + red[1][h];
    } else if (bx < Tn + 64) {
        g_pool[(bx - Tn) * 256 + tid] = 0.f;
    } else if (bx < Tn + 96) {
        // coalesced transpose: 64 k-rows x 128 n per block
        __shared__ __half tile[64][132];
        int k0 = (bx - Tn - 64) * 64;
        #pragma unroll
        for (int p = 0; p < 8; p++) {
            int fidx = p * 256 + tid;
            int row = fidx >> 5, c4 = (fidx & 31) * 4;
            float4 v = *(const float4*)(W1 + (size_t)(k0 + row) * Hn + c4);
            tile[row][c4]     = __float2half_rn(v.x);
            tile[row][c4 + 1] = __float2half_rn(v.y);
            tile[row][c4 + 2] = __float2half_rn(v.z);
            tile[row][c4 + 3] = __float2half_rn(v.w);
        }
        __syncthreads();
        int n = tid >> 1, kh = (tid & 1) * 32;
        __half* dst = g_Wh + (size_t)n * Dsz + k0 + kh;
        uint32_t w[16];
        #pragma unroll
        for (int j = 0; j < 16; j++)
            w[j] = packh2(tile[kh + 2 * j][n], tile[kh + 2 * j + 1][n]);
        #pragma unroll
        for (int j = 0; j < 4; j++)
            *(uint4*)(dst + 8 * j) = make_uint4(w[4 * j], w[4 * j + 1],
                                                w[4 * j + 2], w[4 * j + 3]);
    } else {
        #pragma unroll
        for (int j = 0; j < 4; j++)
            g_venc[j * 256 + tid] = 0.f;
    }
}

// grid (8, 20, 32): z = b*4 + f-quarter, 256 threads (fp32 batch)
__global__ void pool_kernel(const float* __restrict__ batch,
                            const int* __restrict__ seg_len) {
    int b = blockIdx.z >> 2, fq = blockIdx.z & 3, s = blockIdx.y;
    int d = blockIdx.x * 256 + threadIdx.x;
    int len = seg_len[b * Ssz + s];
    int f0 = fq * 50;
    int f1 = min(len, f0 + 50);
    if (f0 >= f1) return;
    const float* p = batch + ((size_t)(b * Ssz + s)) * Fsz * Dsz + d;
    float acc = 0.f;
    #pragma unroll 5
    for (int f = f0; f < f1; f++) acc += p[(size_t)f * Dsz];
    atomicAdd(&g_pool[b * Dsz + d], acc);
}

// grid (Bsz, 24), 128 threads: K-split encoder + concept matvecs -> g_venc
__global__ void enc_kernel(const int* __restrict__ seg_len,
                           const float* __restrict__ concept1,
                           const float* __restrict__ concept2,
                           const float* __restrict__ W_enc,
                           const float* __restrict__ Wc1,
                           const float* __restrict__ Wc2) {
    int b = blockIdx.x, sl = blockIdx.y, h = threadIdx.x;
    float acc = 0.f;
    if (sl < 16) {
        int cnt = 0;
        #pragma unroll
        for (int s = 0; s < Ssz; s++) cnt += seg_len[b * Ssz + s];
        float inv = 1.f / fmaxf((float)cnt, 1.f);
        int d0 = sl * 128;
        #pragma unroll 8
        for (int i = 0; i < 128; i++)
            acc += g_pool[b * Dsz + d0 + i] * W_enc[(size_t)(d0 + i) * Hn + h];
        acc *= inv;
    } else {
        int c0 = (sl - 16) * 38;
        int c1 = min(c0 + 38, CDn);
        #pragma unroll 4
        for (int c = c0; c < c1; c++)
            acc += concept1[b * CDn + c] * Wc1[c * Hn + h]
                 + concept2[b * CDn + c] * Wc2[c * Hn + h];
    }
    atomicAdd(&g_venc[b * Hn + h], acc);
}

// grid Bsz blocks, 1024 threads: relu + topic net + vw3 + softmax
__global__ void small2_kernel(const float* __restrict__ b_enc,
                              const float* __restrict__ Wt1,
                              const float* __restrict__ bt1,
                              const float* __restrict__ Wt2,
                              const float* __restrict__ bt2,
                              const float* __restrict__ W3) {
    int b = blockIdx.x;
    int tid = threadIdx.x;
    int h  = tid & 127;
    int sl = tid >> 7;
    __shared__ float part[8][Hn];
    __shared__ float part2[8][Hn];
    __shared__ float video[Hn];
    __shared__ float th[THn];
    __shared__ float logits[Tn];

    if (sl == 0) video[h] = fmaxf(g_venc[b * Hn + h] + b_enc[h], 0.f);
    __syncthreads();
    {
        float a2 = 0.f, a3 = 0.f;
        int k0 = sl * 16;
        #pragma unroll
        for (int i = 0; i < 16; i++) {
            int k = k0 + i;
            float v = video[k];
            a2 += v * Wt1[k * THn + h];
            a3 += v * W3[k * Hn + h];
        }
        part[sl][h] = a2;
        part2[sl][h] = a3;
    }
    __syncthreads();
    if (sl == 0) {
        float a2 = bt1[h], a3 = 0.f;
        #pragma unroll
        for (int j = 0; j < 8; j++) { a2 += part[j][h]; a3 += part2[j][h]; }
        th[h] = fmaxf(a2, 0.f);
        g_vw3[b * Hn + h] = a3;
    }
    __syncthreads();
    if (tid < Tn) {
        float a4 = bt2[tid];
        #pragma unroll 8
        for (int k = 0; k < THn; k++) a4 += th[k] * Wt2[k * Tn + tid];
        logits[tid] = a4;
    }
    __syncthreads();
    if (tid == 0) {
        float m = -1e30f;
        for (int t = 0; t < Tn; t++) m = fmaxf(m, logits[t]);
        float ssum = 0.f;
        for (int t = 0; t < Tn; t++) { float e = __expf(logits[t] - m); logits[t] = e; ssum += e; }
        float invs = 1.f / ssum;
        for (int t = 0; t < Tn; t++) g_probs[b * Tn + t] = logits[t] * invs;
    }
}

// ---------------------------------------------------------------------------
// gemm_main: single-fp16 GEMM mainloop only (batch @ W1) -> g_acc.
// BM=128, BN=128, KCH=64, 512 threads (16 warps, 32x32 warp tiles),
// double-buffered smem, A register-prefetch distance 2, cp.async B.
// ---------------------------------------------------------------------------
#define KCH   64
#define NCHK  (Dsz / KCH)               // 32
#define STAGE 32768                     // A 16K | B 16K
#define OFF_B  16384
#define SM_BYTES (2 * STAGE + 2048)

__global__ __launch_bounds__(512, 1)
void gemm_main_kernel(const float* __restrict__ batch) {
    extern __shared__ char smem_raw[];
    uint32_t sb0 = smem_u32(smem_raw);
    uint32_t sb = (sb0 + 1023) & ~1023u;
    char* smem = smem_raw + (sb - sb0);

    int tid = threadIdx.x;
    int wid = tid >> 5, lane = tid & 31;
    int m0 = blockIdx.x * 128;

    // ---- per-thread A-load mapping: row = tid>>2, 16 floats at (tid&3)*16 ----
    int lrow = tid >> 2;
    int lq = tid & 3;
    const float* aptr = batch + (size_t)(m0 + lrow) * Dsz + lq * 16;
    uint32_t a_sts[2];
    #pragma unroll
    for (int g = 0; g < 2; g++)
        a_sts[g] = (uint32_t)lrow * 128 +
                   (((uint32_t)(lq * 32 + g * 16)) ^ (((uint32_t)lrow & 7) << 4));
    // B cp.async: 2 x 16B per thread per chunk
    int brow_g[2], bc16[2];
    uint32_t b_dst[2];
    #pragma unroll
    for (int j = 0; j < 2; j++) {
        int gid = tid + j * 512;
        brow_g[j] = gid >> 3;
        bc16[j] = gid & 7;
        b_dst[j] = (uint32_t)brow_g[j] * 128 +
                   (((uint32_t)(bc16[j] * 16)) ^ (((uint32_t)brow_g[j] & 7) << 4));
    }

    // ---- per-warp fragment mapping: 16 warps, warp tile 32x32 ----
    int wm = wid >> 2, wn = wid & 3;
    int lr = lane & 7, s1 = (lane >> 3) & 1, s2 = lane >> 4;
    uint32_t a_base[2], a_xor[2];
    #pragma unroll
    for (int mt = 0; mt < 2; mt++) {
        int arow = wm * 32 + mt * 16 + s1 * 8 + lr;
        a_base[mt] = (uint32_t)arow * 128;
        a_xor[mt] = ((uint32_t)arow & 7) << 4;
    }
    uint32_t b_base[2], b_xor[2];
    #pragma unroll
    for (int np = 0; np < 2; np++) {
        int brow = wn * 32 + np * 16 + s2 * 8 + lr;
        b_base[np] = (uint32_t)brow * 128;
        b_xor[np] = ((uint32_t)brow & 7) << 4;
    }
    uint32_t a_kadd = (uint32_t)(s2 * 16);
    uint32_t b_kadd = (uint32_t)(s1 * 16);

    float acc[2][4][4];
    #pragma unroll
    for (int mt = 0; mt < 2; mt++)
        #pragma unroll
        for (int nt = 0; nt < 4; nt++)
            #pragma unroll
            for (int e = 0; e < 4; e++) acc[mt][nt][e] = 0.f;

    // ---- prologue: LDG A chunks 0,1 into ar[0],ar[1]; cp.async B 0,1 ----
    float4 ar[2][4];
    #pragma unroll
    for (int g = 0; g < 4; g++) {
        ar[0][g] = ((const float4*)aptr)[g];
        ar[1][g] = ((const float4*)(aptr + KCH))[g];
    }
    #pragma unroll
    for (int c = 0; c < 2; c++) {
        uint32_t bB = sb + c * STAGE + OFF_B;
        int k0 = c * KCH;
        #pragma unroll
        for (int j = 0; j < 2; j++)
            CP_ASYNC16(bB + b_dst[j],
                       g_Wh + (size_t)brow_g[j] * Dsz + k0 + bc16[j] * 8);
        CP_COMMIT();
    }

    for (int c = 0; c < NCHK; c++) {
        int p = c & 1;
        if (c == NCHK - 1) { CP_WAIT0(); } else { CP_WAIT1(); }

        // STS A chunk c (fp32 -> fp16) from ar[p]
        {
            char* bah = smem + p * STAGE;
            uint32_t hi[4];
            #pragma unroll
            for (int g = 0; g < 2; g++) {
                float4 v0 = ar[p][2 * g], v1 = ar[p][2 * g + 1];
                hi[0] = packh2(__float2half_rn(v0.x), __float2half_rn(v0.y));
                hi[1] = packh2(__float2half_rn(v0.z), __float2half_rn(v0.w));
                hi[2] = packh2(__float2half_rn(v1.x), __float2half_rn(v1.y));
                hi[3] = packh2(__float2half_rn(v1.z), __float2half_rn(v1.w));
                *(uint4*)(bah + a_sts[g]) = make_uint4(hi[0], hi[1], hi[2], hi[3]);
            }
        }
        __syncthreads();

        // prefetch A chunk c+2 into ar[p] (distance 2)
        if (c + 2 < NCHK) {
            const float4* ap = (const float4*)(aptr + (c + 2) * KCH);
            #pragma unroll
            for (int g = 0; g < 4; g++) ar[p][g] = ap[g];
        }

        // compute on stage p: 4 k16 steps
        {
            uint32_t Ahb = sb + p * STAGE;
            uint32_t Bb  = Ahb + OFF_B;
            #pragma unroll
            for (int ks = 0; ks < 4; ks++) {
                uint32_t ka = (uint32_t)(ks * 32) + a_kadd;
                uint32_t kb = (uint32_t)(ks * 32) + b_kadd;
                uint32_t af[2][4];
                #pragma unroll
                for (int mt = 0; mt < 2; mt++)
                    LDSM4(af[mt][0], af[mt][1], af[mt][2], af[mt][3],
                          Ahb + a_base[mt] + (ka ^ a_xor[mt]));
                uint32_t bf[4][2];
                #pragma unroll
                for (int np = 0; np < 2; np++)
                    LDSM4(bf[2 * np][0], bf[2 * np][1], bf[2 * np + 1][0], bf[2 * np + 1][1],
                          Bb + b_base[np] + (kb ^ b_xor[np]));
                #pragma unroll
                for (int mt = 0; mt < 2; mt++)
                    #pragma unroll
                    for (int nt = 0; nt < 4; nt++)
                        mma16816h(acc[mt][nt], af[mt], bf[nt]);
            }
        }
        __syncthreads();

        // issue B cp.async for chunk c+2 into stage p
        if (c + 2 < NCHK) {
            uint32_t bB = sb + p * STAGE + OFF_B;
            int k0 = (c + 2) * KCH;
            #pragma unroll
            for (int j = 0; j < 2; j++)
                CP_ASYNC16(bB + b_dst[j],
                           g_Wh + (size_t)brow_g[j] * Dsz + k0 + bc16[j] * 8);
            CP_COMMIT();
        }
    }

    // ---- store acc coalesced: g_acc[block][j][tid] ----
    float4* dst = g_acc + (size_t)blockIdx.x * 4096;
    #pragma unroll
    for (int mt = 0; mt < 2; mt++)
        #pragma unroll
        for (int nt = 0; nt < 4; nt++)
            dst[(mt * 4 + nt) * 512 + tid] =
                make_float4(acc[mt][nt][0], acc[mt][nt][1],
                            acc[mt][nt][2], acc[mt][nt][3]);
}

// ---------------------------------------------------------------------------
// epi: load g_acc (same mapping) + bias/vw3 + 20-topic loop -> out.
// grid 250 x 512
// ---------------------------------------------------------------------------
__global__ __launch_bounds__(512, 1)
void epi_kernel(const float* __restrict__ b1,
                const float* __restrict__ w_out,
                const float* __restrict__ b_out_p,
                float* __restrict__ out,
                int out_size) {
    __shared__ float s_con[Tn * Hn];
    __shared__ float s_vw3[Bsz * Hn];
    __shared__ float s_b1v[Hn];
    __shared__ float s_wo[Hn];
    __shared__ float s_prob[Bsz * Tn];
    __shared__ float s_red[128 * 4 * 4];

    int tid = threadIdx.x;
    int wid = tid >> 5, lane = tid & 31;
    int m0 = blockIdx.x * 128;

    for (int i = tid; i < Tn * Hn; i += 512) s_con[i] = g_contrib[i];
    for (int i = tid; i < Bsz * Hn; i += 512) s_vw3[i] = g_vw3[i];
    if (tid < Hn) { s_b1v[tid] = b1[tid]; s_wo[tid] = w_out[tid]; }
    if (tid < Bsz * Tn) s_prob[tid] = g_probs[tid];
    __syncthreads();

    // load acc (same per-thread layout as gemm_main store)
    float acc[2][4][4];
    {
        const float4* src = g_acc + (size_t)blockIdx.x * 4096;
        #pragma unroll
        for (int mt = 0; mt < 2; mt++)
            #pragma unroll
            for (int nt = 0; nt < 4; nt++) {
                float4 v = src[(mt * 4 + nt) * 512 + tid];
                acc[mt][nt][0] = v.x; acc[mt][nt][1] = v.y;
                acc[mt][nt][2] = v.z; acc[mt][nt][3] = v.w;
            }
    }

    int wm = wid >> 2, wn = wid & 3;
    int r = lane >> 2, q = lane & 3;
    float bo = b_out_p[0];

    #pragma unroll
    for (int mt = 0; mt < 2; mt++) {
        int rg0 = m0 + wm * 32 + mt * 16 + r;
        int rg1 = rg0 + 8;
        int b0 = rg0 / ROWS_PER_B;
        int b1i = rg1 / ROWS_PER_B;
        #pragma unroll
        for (int nt = 0; nt < 4; nt++)
            #pragma unroll
            for (int e = 0; e < 2; e++) {
                int col = wn * 32 + nt * 8 + 2 * q + e;
                acc[mt][nt][e]     += s_b1v[col] + s_vw3[b0 * Hn + col];
                acc[mt][nt][2 + e] += s_b1v[col] + s_vw3[b1i * Hn + col];
            }
    }

    float wv[4][2];
    #pragma unroll
    for (int nt = 0; nt < 4; nt++)
        #pragma unroll
        for (int e = 0; e < 2; e++)
            wv[nt][e] = s_wo[wn * 32 + nt * 8 + 2 * q + e];

    float orow = 0.f;
    int myrow = m0 + (tid & 127);
    int myb = myrow / ROWS_PER_B;

    for (int tg = 0; tg < 5; tg++) {
        #pragma unroll
        for (int mt = 0; mt < 2; mt++) {
            float p0[4] = {0.f, 0.f, 0.f, 0.f};
            float p1[4] = {0.f, 0.f, 0.f, 0.f};
            #pragma unroll
            for (int tt = 0; tt < 4; tt++) {
                int t = tg * 4 + tt;
                #pragma unroll
                for (int nt = 0; nt < 4; nt++)
                    #pragma unroll
                    for (int e = 0; e < 2; e++) {
                        float cv = s_con[t * Hn + wn * 32 + nt * 8 + 2 * q + e];
                        p0[tt] = fmaf(fmaxf(acc[mt][nt][e]     + cv, 0.f), wv[nt][e], p0[tt]);
                        p1[tt] = fmaf(fmaxf(acc[mt][nt][2 + e] + cv, 0.f), wv[nt][e], p1[tt]);
                    }
            }
            #pragma unroll
            for (int tt = 0; tt < 4; tt++) {
                p0[tt] += __shfl_xor_sync(0xffffffffu, p0[tt], 1);
                p0[tt] += __shfl_xor_sync(0xffffffffu, p0[tt], 2);
                p1[tt] += __shfl_xor_sync(0xffffffffu, p1[tt], 1);
                p1[tt] += __shfl_xor_sync(0xffffffffu, p1[tt], 2);
            }
            if (q == 0) {
                int row0 = wm * 32 + mt * 16 + r;
                #pragma unroll
                for (int tt = 0; tt < 4; tt++) {
                    s_red[(row0 * 4 + wn) * 4 + tt]       = p0[tt];
                    s_red[((row0 + 8) * 4 + wn) * 4 + tt] = p1[tt];
                }
            }
        }
        __syncthreads();
        if (tid < 128) {
            #pragma unroll
            for (int tt = 0; tt < 4; tt++) {
                int t = tg * 4 + tt;
                float s = s_red[(tid * 4 + 0) * 4 + tt] + s_red[(tid * 4 + 1) * 4 + tt]
                        + s_red[(tid * 4 + 2) * 4 + tt] + s_red[(tid * 4 + 3) * 4 + tt] + bo;
                float sig = 1.f / (1.f + __expf(-s));
                float sc = sig * s_prob[myb * Tn + t] - 0.01f;
                orow += fmaxf(sc, 0.f);
            }
        }
        __syncthreads();
    }

    if (tid < 128) {
        float v = orow * (1.f / (float)Tn);
        out[myrow] = v;
        if (out_size >= 2 * Mrows) out[Mrows + myrow] = v;
    }
}

// ---------------------------------------------------------------------------
extern "C" void kernel_launch(void* const* d_in, const int* in_sizes, int n_in,
                              void* d_out, int out_size) {
    const float* batch     = (const float*)d_in[0];
    const int*   seg_len   = (const int*)  d_in[1];
    const float* concept1  = (const float*)d_in[2];
    const float* concept2  = (const float*)d_in[3];
    const float* W_enc     = (const float*)d_in[4];
    const float* b_enc     = (const float*)d_in[5];
    const float* Wc1       = (const float*)d_in[6];
    const float* Wc2       = (const float*)d_in[7];
    const float* Wt1       = (const float*)d_in[8];
    const float* bt1       = (const float*)d_in[9];
    const float* Wt2       = (const float*)d_in[10];
    const float* bt2       = (const float*)d_in[11];
    const float* topic_emb = (const float*)d_in[12];
    const float* W1        = (const float*)d_in[13];
    const float* b1        = (const float*)d_in[14];
    const float* W2        = (const float*)d_in[15];
    const float* W3        = (const float*)d_in[16];
    const float* w_out     = (const float*)d_in[17];
    const float* b_out     = (const float*)d_in[18];
    float* out = (float*)d_out;

    cudaFuncSetAttribute(gemm_main_kernel,
                         cudaFuncAttributeMaxDynamicSharedMemorySize, SM_BYTES);

    prep_kernel<<<Tn + 64 + 32 + 1, 256>>>(W1, topic_emb, W2);
    pool_kernel<<<dim3(Dsz / 256, Ssz, Bsz * 4), 256>>>(batch, seg_len);
    enc_kernel<<<dim3(Bsz, 24), 128>>>(seg_len, concept1, concept2,
                                       W_enc, Wc1, Wc2);
    small2_kernel<<<Bsz, 1024>>>(b_enc, Wt1, bt1, Wt2, bt2, W3);
    gemm_main_kernel<<<Mrows / 128, 512, SM_BYTES>>>(batch);
    epi_kernel<<<Mrows / 128, 512>>>(b1, w_out, b_out, out, out_size);
}

// round 12
// speedup vs baseline: 1.3032x; 1.3032x over previous
#include <cuda_runtime.h>
#include <cuda_fp16.h>
#include <stdint.h>

// Problem constants
#define Bsz 8
#define Ssz 20
#define Fsz 200
#define Dsz 2048
#define Tn  20
#define En  128
#define Hn  128
#define CDn 300
#define THn 128
#define Mrows (Bsz*Ssz*Fsz)     // 32000
#define ROWS_PER_B (Ssz*Fsz)    // 4000

// Scratch (no allocations allowed)
__device__ float g_pool[Bsz*Dsz];
__device__ float g_venc[Bsz*Hn];                  // pooled@W_enc + concept terms
__device__ float g_vw3[Bsz*Hn];
__device__ float g_probs[Bsz*Tn];
__device__ float g_contrib[Tn*Hn];
__device__ __half g_Wh[Hn*Dsz];                   // W1^T fp16  [n][k]

// ---------------------------------------------------------------------------
__device__ __forceinline__ uint32_t smem_u32(const void* p) {
    uint32_t a;
    asm("{ .reg .u64 t; cvta.to.shared.u64 t, %1; cvt.u32.u64 %0, t; }"
        : "=r"(a) : "l"(p));
    return a;
}
__device__ __forceinline__ void mma16816h(float* d, const uint32_t* a, const uint32_t* b) {
    asm volatile(
        "mma.sync.aligned.m16n8k16.row.col.f32.f16.f16.f32 "
        "{%0,%1,%2,%3}, {%4,%5,%6,%7}, {%8,%9}, {%0,%1,%2,%3};"
        : "+f"(d[0]), "+f"(d[1]), "+f"(d[2]), "+f"(d[3])
        : "r"(a[0]), "r"(a[1]), "r"(a[2]), "r"(a[3]), "r"(b[0]), "r"(b[1]));
}
#define LDSM4(r0, r1, r2, r3, addr) \
    asm volatile("ldmatrix.sync.aligned.m8n8.x4.shared.b16 {%0,%1,%2,%3}, [%4];" \
                 : "=r"(r0), "=r"(r1), "=r"(r2), "=r"(r3) : "r"(addr))
#define CP_ASYNC16(dst, src) \
    asm volatile("cp.async.cg.shared.global [%0], [%1], 16;" :: "r"(dst), "l"(src))
#define CP_COMMIT() asm volatile("cp.async.commit_group;")
#define CP_WAIT1()  asm volatile("cp.async.wait_group 1;")
#define CP_WAIT0()  asm volatile("cp.async.wait_group 0;")

__device__ __forceinline__ uint32_t packh2(__half a, __half b) {
    __half2 h = __halves2half2(a, b);
    return *(uint32_t*)&h;
}

// ---------------------------------------------------------------------------
// prep: contrib (0..19) + zero g_pool (20..83) + W1 transpose (84..115)
// + zero g_venc (116).  grid 117 x 256
// ---------------------------------------------------------------------------
__global__ void prep_kernel(const float* __restrict__ W1,
                            const float* __restrict__ topic_emb,
                            const float* __restrict__ W2) {
    int bx = blockIdx.x, tid = threadIdx.x;
    if (bx < Tn) {
        __shared__ float red[2][Hn];
        int h = tid & 127, e2 = tid >> 7;
        float acc = 0.f;
        int e0 = e2 * 64;
        #pragma unroll 8
        for (int e = e0; e < e0 + 64; e++)
            acc += topic_emb[bx * En + e] * W2[e * Hn + h];
        red[e2][h] = acc;
        __syncthreads();
        if (e2 == 0) g_contrib[bx * Hn + h] = red[0][h] + red[1][h];
    } else if (bx < Tn + 64) {
        g_pool[(bx - Tn) * 256 + tid] = 0.f;
    } else if (bx < Tn + 96) {
        // coalesced transpose: 64 k-rows x 128 n per block
        __shared__ __half tile[64][132];
        int k0 = (bx - Tn - 64) * 64;
        #pragma unroll
        for (int p = 0; p < 8; p++) {
            int fidx = p * 256 + tid;
            int row = fidx >> 5, c4 = (fidx & 31) * 4;
            float4 v = *(const float4*)(W1 + (size_t)(k0 + row) * Hn + c4);
            tile[row][c4]     = __float2half_rn(v.x);
            tile[row][c4 + 1] = __float2half_rn(v.y);
            tile[row][c4 + 2] = __float2half_rn(v.z);
            tile[row][c4 + 3] = __float2half_rn(v.w);
        }
        __syncthreads();
        int n = tid >> 1, kh = (tid & 1) * 32;
        __half* dst = g_Wh + (size_t)n * Dsz + k0 + kh;
        uint32_t w[16];
        #pragma unroll
        for (int j = 0; j < 16; j++)
            w[j] = packh2(tile[kh + 2 * j][n], tile[kh + 2 * j + 1][n]);
        #pragma unroll
        for (int j = 0; j < 4; j++)
            *(uint4*)(dst + 8 * j) = make_uint4(w[4 * j], w[4 * j + 1],
                                                w[4 * j + 2], w[4 * j + 3]);
    } else {
        #pragma unroll
        for (int j = 0; j < 4; j++)
            g_venc[j * 256 + tid] = 0.f;
    }
}

// grid (8, 20, 32): z = b*4 + f-quarter, 256 threads (fp32 batch)
__global__ void pool_kernel(const float* __restrict__ batch,
                            const int* __restrict__ seg_len) {
    int b = blockIdx.z >> 2, fq = blockIdx.z & 3, s = blockIdx.y;
    int d = blockIdx.x * 256 + threadIdx.x;
    int len = seg_len[b * Ssz + s];
    int f0 = fq * 50;
    int f1 = min(len, f0 + 50);
    if (f0 >= f1) return;
    const float* p = batch + ((size_t)(b * Ssz + s)) * Fsz * Dsz + d;
    float acc = 0.f;
    #pragma unroll 5
    for (int f = f0; f < f1; f++) acc += p[(size_t)f * Dsz];
    atomicAdd(&g_pool[b * Dsz + d], acc);
}

// grid (Bsz, 24), 128 threads: K-split encoder + concept matvecs -> g_venc
__global__ void enc_kernel(const int* __restrict__ seg_len,
                           const float* __restrict__ concept1,
                           const float* __restrict__ concept2,
                           const float* __restrict__ W_enc,
                           const float* __restrict__ Wc1,
                           const float* __restrict__ Wc2) {
    int b = blockIdx.x, sl = blockIdx.y, h = threadIdx.x;
    float acc = 0.f;
    if (sl < 16) {
        int cnt = 0;
        #pragma unroll
        for (int s = 0; s < Ssz; s++) cnt += seg_len[b * Ssz + s];
        float inv = 1.f / fmaxf((float)cnt, 1.f);
        int d0 = sl * 128;
        #pragma unroll 8
        for (int i = 0; i < 128; i++)
            acc += g_pool[b * Dsz + d0 + i] * W_enc[(size_t)(d0 + i) * Hn + h];
        acc *= inv;
    } else {
        int c0 = (sl - 16) * 38;
        int c1 = min(c0 + 38, CDn);
        #pragma unroll 4
        for (int c = c0; c < c1; c++)
            acc += concept1[b * CDn + c] * Wc1[c * Hn + h]
                 + concept2[b * CDn + c] * Wc2[c * Hn + h];
    }
    atomicAdd(&g_venc[b * Hn + h], acc);
}

// grid Bsz blocks, 1024 threads: relu + topic net + vw3 + softmax
// Weight loads hoisted ABOVE the barrier so their latency overlaps the
// video computation instead of serializing behind it.
__global__ void small2_kernel(const float* __restrict__ b_enc,
                              const float* __restrict__ Wt1,
                              const float* __restrict__ bt1,
                              const float* __restrict__ Wt2,
                              const float* __restrict__ bt2,
                              const float* __restrict__ W3) {
    int b = blockIdx.x;
    int tid = threadIdx.x;
    int h  = tid & 127;
    int sl = tid >> 7;
    __shared__ float part[8][Hn];
    __shared__ float part2[8][Hn];
    __shared__ float video[Hn];
    __shared__ float th[THn];
    __shared__ float logits[Tn];

    // hoisted weight loads (independent of video)
    int k0 = sl * 16;
    float wt1r[16], w3r[16];
    #pragma unroll
    for (int i = 0; i < 16; i++) {
        wt1r[i] = Wt1[(k0 + i) * THn + h];
        w3r[i]  = W3[(k0 + i) * Hn + h];
    }

    if (sl == 0) video[h] = fmaxf(g_venc[b * Hn + h] + b_enc[h], 0.f);
    __syncthreads();
    {
        float a2 = 0.f, a3 = 0.f;
        #pragma unroll
        for (int i = 0; i < 16; i++) {
            float v = video[k0 + i];
            a2 += v * wt1r[i];
            a3 += v * w3r[i];
        }
        part[sl][h] = a2;
        part2[sl][h] = a3;
    }
    __syncthreads();
    if (sl == 0) {
        float a2 = bt1[h], a3 = 0.f;
        #pragma unroll
        for (int j = 0; j < 8; j++) { a2 += part[j][h]; a3 += part2[j][h]; }
        th[h] = fmaxf(a2, 0.f);
        g_vw3[b * Hn + h] = a3;
    }
    __syncthreads();
    if (tid < Tn) {
        float a4 = bt2[tid];
        #pragma unroll 8
        for (int k = 0; k < THn; k++) a4 += th[k] * Wt2[k * Tn + tid];
        logits[tid] = a4;
    }
    __syncthreads();
    if (tid == 0) {
        float m = -1e30f;
        for (int t = 0; t < Tn; t++) m = fmaxf(m, logits[t]);
        float ssum = 0.f;
        for (int t = 0; t < Tn; t++) { float e = __expf(logits[t] - m); logits[t] = e; ssum += e; }
        float invs = 1.f / ssum;
        for (int t = 0; t < Tn; t++) g_probs[b * Tn + t] = logits[t] * invs;
    }
}

// ---------------------------------------------------------------------------
// single-fp16 GEMM (batch @ W1) + fused topic epilogue.  (R7/R10 config)
// BM=128, BN=128, KCH=64, 512 threads (16 warps, 32x32 warp tiles),
// double-buffered, ldmatrix + cp.async.
// ---------------------------------------------------------------------------
#define KCH   64
#define NCHK  (Dsz / KCH)               // 32
#define STAGE 32768                     // Ah 16K | B 16K
#define OFF_B  16384
#define SM_CONTRIB 65536                // 10240 B
#define SM_VW3     75776                // 4096 B
#define SM_B1      79872                // 512 B
#define SM_WOUT    80384                // 512 B
#define SM_PROBS   80896                // 768 B
#define SM_RED     81664                // 8192 B  [128][4][4]
#define SM_BYTES   (89856 + 1024)

__global__ __launch_bounds__(512, 1)
void gemm_tc_kernel(const float* __restrict__ batch,
                    const float* __restrict__ b1,
                    const float* __restrict__ w_out,
                    const float* __restrict__ b_out_p,
                    float* __restrict__ out,
                    int out_size) {
    extern __shared__ char smem_raw[];
    uint32_t sb0 = smem_u32(smem_raw);
    uint32_t sb = (sb0 + 1023) & ~1023u;
    char* smem = smem_raw + (sb - sb0);

    int tid = threadIdx.x;
    int wid = tid >> 5, lane = tid & 31;
    int m0 = blockIdx.x * 128;

    // epilogue-constant preload (covered by first in-loop __syncthreads)
    for (int i = tid; i < Tn * Hn; i += 512)
        ((float*)(smem + SM_CONTRIB))[i] = g_contrib[i];
    for (int i = tid; i < Bsz * Hn; i += 512)
        ((float*)(smem + SM_VW3))[i] = g_vw3[i];
    if (tid < Hn) {
        ((float*)(smem + SM_B1))[tid] = b1[tid];
        ((float*)(smem + SM_WOUT))[tid] = w_out[tid];
    }
    if (tid < Bsz * Tn)
        ((float*)(smem + SM_PROBS))[tid] = g_probs[tid];

    // ---- per-thread A-load mapping: row = tid>>2, 16 floats at (tid&3)*16 ----
    int lrow = tid >> 2;
    int lq = tid & 3;
    const float* aptr = batch + (size_t)(m0 + lrow) * Dsz + lq * 16;
    uint32_t a_sts[2];
    #pragma unroll
    for (int g = 0; g < 2; g++)
        a_sts[g] = (uint32_t)lrow * 128 +
                   (((uint32_t)(lq * 32 + g * 16)) ^ (((uint32_t)lrow & 7) << 4));
    // B cp.async: 2 x 16B per thread per chunk
    int brow_g[2], bc16[2];
    uint32_t b_dst[2];
    #pragma unroll
    for (int j = 0; j < 2; j++) {
        int gid = tid + j * 512;
        brow_g[j] = gid >> 3;
        bc16[j] = gid & 7;
        b_dst[j] = (uint32_t)brow_g[j] * 128 +
                   (((uint32_t)(bc16[j] * 16)) ^ (((uint32_t)brow_g[j] & 7) << 4));
    }

    // ---- per-warp fragment mapping: 16 warps, warp tile 32x32 ----
    int wm = wid >> 2, wn = wid & 3;
    int lr = lane & 7, s1 = (lane >> 3) & 1, s2 = lane >> 4;
    uint32_t a_base[2], a_xor[2];
    #pragma unroll
    for (int mt = 0; mt < 2; mt++) {
        int arow = wm * 32 + mt * 16 + s1 * 8 + lr;
        a_base[mt] = (uint32_t)arow * 128;
        a_xor[mt] = ((uint32_t)arow & 7) << 4;
    }
    uint32_t b_base[2], b_xor[2];
    #pragma unroll
    for (int np = 0; np < 2; np++) {
        int brow = wn * 32 + np * 16 + s2 * 8 + lr;
        b_base[np] = (uint32_t)brow * 128;
        b_xor[np] = ((uint32_t)brow & 7) << 4;
    }
    uint32_t a_kadd = (uint32_t)(s2 * 16);
    uint32_t b_kadd = (uint32_t)(s1 * 16);

    float acc[2][4][4];
    #pragma unroll
    for (int mt = 0; mt < 2; mt++)
        #pragma unroll
        for (int nt = 0; nt < 4; nt++)
            #pragma unroll
            for (int e = 0; e < 4; e++) acc[mt][nt][e] = 0.f;

    // ---- prologue: LDG A chunk0 ; cp.async B chunk0->st0, chunk1->st1 ----
    float4 ar[4];
    #pragma unroll
    for (int g = 0; g < 4; g++) ar[g] = ((const float4*)aptr)[g];
    #pragma unroll
    for (int c = 0; c < 2; c++) {
        uint32_t bB = sb + c * STAGE + OFF_B;
        int k0 = c * KCH;
        #pragma unroll
        for (int j = 0; j < 2; j++)
            CP_ASYNC16(bB + b_dst[j],
                       g_Wh + (size_t)brow_g[j] * Dsz + k0 + bc16[j] * 8);
        CP_COMMIT();
    }

    for (int c = 0; c < NCHK; c++) {
        int p = c & 1;
        if (c == NCHK - 1) { CP_WAIT0(); } else { CP_WAIT1(); }

        // STS A (fp32 -> fp16)
        {
            char* bah = smem + p * STAGE;
            uint32_t hi[4];
            #pragma unroll
            for (int g = 0; g < 2; g++) {
                float4 v0 = ar[2 * g], v1 = ar[2 * g + 1];
                hi[0] = packh2(__float2half_rn(v0.x), __float2half_rn(v0.y));
                hi[1] = packh2(__float2half_rn(v0.z), __float2half_rn(v0.w));
                hi[2] = packh2(__float2half_rn(v1.x), __float2half_rn(v1.y));
                hi[3] = packh2(__float2half_rn(v1.z), __float2half_rn(v1.w));
                *(uint4*)(bah + a_sts[g]) = make_uint4(hi[0], hi[1], hi[2], hi[3]);
            }
        }
        __syncthreads();

        // prefetch next A chunk
        if (c + 1 < NCHK) {
            const float4* ap = (const float4*)(aptr + (c + 1) * KCH);
            #pragma unroll
            for (int g = 0; g < 4; g++) ar[g] = ap[g];
        }

        // compute on stage p: 4 k16 steps
        {
            uint32_t Ahb = sb + p * STAGE;
            uint32_t Bb  = Ahb + OFF_B;
            #pragma unroll
            for (int ks = 0; ks < 4; ks++) {
                uint32_t ka = (uint32_t)(ks * 32) + a_kadd;
                uint32_t kb = (uint32_t)(ks * 32) + b_kadd;
                uint32_t af[2][4];
                #pragma unroll
                for (int mt = 0; mt < 2; mt++)
                    LDSM4(af[mt][0], af[mt][1], af[mt][2], af[mt][3],
                          Ahb + a_base[mt] + (ka ^ a_xor[mt]));
                uint32_t bf[4][2];
                #pragma unroll
                for (int np = 0; np < 2; np++)
                    LDSM4(bf[2 * np][0], bf[2 * np][1], bf[2 * np + 1][0], bf[2 * np + 1][1],
                          Bb + b_base[np] + (kb ^ b_xor[np]));
                #pragma unroll
                for (int mt = 0; mt < 2; mt++)
                    #pragma unroll
                    for (int nt = 0; nt < 4; nt++)
                        mma16816h(acc[mt][nt], af[mt], bf[nt]);
            }
        }
        __syncthreads();

        // issue B cp.async for chunk c+2 into stage p
        if (c + 2 < NCHK) {
            uint32_t bB = sb + p * STAGE + OFF_B;
            int k0 = (c + 2) * KCH;
            #pragma unroll
            for (int j = 0; j < 2; j++)
                CP_ASYNC16(bB + b_dst[j],
                           g_Wh + (size_t)brow_g[j] * Dsz + k0 + bc16[j] * 8);
            CP_COMMIT();
        }
    }

    // ----- Epilogue: base = acc + b1 + vw3[b]; 20-topic loop, 4/sync -----
    float* s_red   = (float*)(smem + SM_RED);          // [128][4][4]
    const float* s_vw3  = (const float*)(smem + SM_VW3);
    const float* s_b1v  = (const float*)(smem + SM_B1);
    const float* s_wo   = (const float*)(smem + SM_WOUT);
    const float* s_prob = (const float*)(smem + SM_PROBS);
    const float* s_con  = (const float*)(smem + SM_CONTRIB);
    float bo = b_out_p[0];
    int r = lane >> 2, q = lane & 3;

    #pragma unroll
    for (int mt = 0; mt < 2; mt++) {
        int rg0 = m0 + wm * 32 + mt * 16 + r;
        int rg1 = rg0 + 8;
        int b0 = rg0 / ROWS_PER_B;
        int b1i = rg1 / ROWS_PER_B;
        #pragma unroll
        for (int nt = 0; nt < 4; nt++)
            #pragma unroll
            for (int e = 0; e < 2; e++) {
                int col = wn * 32 + nt * 8 + 2 * q + e;
                acc[mt][nt][e]     += s_b1v[col] + s_vw3[b0 * Hn + col];
                acc[mt][nt][2 + e] += s_b1v[col] + s_vw3[b1i * Hn + col];
            }
    }

    float wv[4][2];
    #pragma unroll
    for (int nt = 0; nt < 4; nt++)
        #pragma unroll
        for (int e = 0; e < 2; e++)
            wv[nt][e] = s_wo[wn * 32 + nt * 8 + 2 * q + e];

    float orow = 0.f;     // per-row accumulator for threads tid<128
    int myrow = m0 + (tid & 127);
    int myb = myrow / ROWS_PER_B;

    for (int tg = 0; tg < 5; tg++) {
        #pragma unroll
        for (int mt = 0; mt < 2; mt++) {
            float p0[4] = {0.f, 0.f, 0.f, 0.f};
            float p1[4] = {0.f, 0.f, 0.f, 0.f};
            #pragma unroll
            for (int tt = 0; tt < 4; tt++) {
                int t = tg * 4 + tt;
                #pragma unroll
                for (int nt = 0; nt < 4; nt++)
                    #pragma unroll
                    for (int e = 0; e < 2; e++) {
                        float cv = s_con[t * Hn + wn * 32 + nt * 8 + 2 * q + e];
                        p0[tt] = fmaf(fmaxf(acc[mt][nt][e]     + cv, 0.f), wv[nt][e], p0[tt]);
                        p1[tt] = fmaf(fmaxf(acc[mt][nt][2 + e] + cv, 0.f), wv[nt][e], p1[tt]);
                    }
            }
            #pragma unroll
            for (int tt = 0; tt < 4; tt++) {
                p0[tt] += __shfl_xor_sync(0xffffffffu, p0[tt], 1);
                p0[tt] += __shfl_xor_sync(0xffffffffu, p0[tt], 2);
                p1[tt] += __shfl_xor_sync(0xffffffffu, p1[tt], 1);
                p1[tt] += __shfl_xor_sync(0xffffffffu, p1[tt], 2);
            }
            if (q == 0) {
                int row0 = wm * 32 + mt * 16 + r;
                #pragma unroll
                for (int tt = 0; tt < 4; tt++) {
                    s_red[(row0 * 4 + wn) * 4 + tt]       = p0[tt];
                    s_red[((row0 + 8) * 4 + wn) * 4 + tt] = p1[tt];
                }
            }
        }
        __syncthreads();
        if (tid < 128) {
            #pragma unroll
            for (int tt = 0; tt < 4; tt++) {
                int t = tg * 4 + tt;
                float s = s_red[(tid * 4 + 0) * 4 + tt] + s_red[(tid * 4 + 1) * 4 + tt]
                        + s_red[(tid * 4 + 2) * 4 + tt] + s_red[(tid * 4 + 3) * 4 + tt] + bo;
                float sig = 1.f / (1.f + __expf(-s));
                float sc = sig * s_prob[myb * Tn + t] - 0.01f;
                orow += fmaxf(sc, 0.f);
            }
        }
        __syncthreads();
    }

    if (tid < 128) {
        float v = orow * (1.f / (float)Tn);
        out[myrow] = v;
        if (out_size >= 2 * Mrows) out[Mrows + myrow] = v;
    }
}

// ---------------------------------------------------------------------------
extern "C" void kernel_launch(void* const* d_in, const int* in_sizes, int n_in,
                              void* d_out, int out_size) {
    const float* batch     = (const float*)d_in[0];
    const int*   seg_len   = (const int*)  d_in[1];
    const float* concept1  = (const float*)d_in[2];
    const float* concept2  = (const float*)d_in[3];
    const float* W_enc     = (const float*)d_in[4];
    const float* b_enc     = (const float*)d_in[5];
    const float* Wc1       = (const float*)d_in[6];
    const float* Wc2       = (const float*)d_in[7];
    const float* Wt1       = (const float*)d_in[8];
    const float* bt1       = (const float*)d_in[9];
    const float* Wt2       = (const float*)d_in[10];
    const float* bt2       = (const float*)d_in[11];
    const float* topic_emb = (const float*)d_in[12];
    const float* W1        = (const float*)d_in[13];
    const float* b1        = (const float*)d_in[14];
    const float* W2        = (const float*)d_in[15];
    const float* W3        = (const float*)d_in[16];
    const float* w_out     = (const float*)d_in[17];
    const float* b_out     = (const float*)d_in[18];
    float* out = (float*)d_out;

    cudaFuncSetAttribute(gemm_tc_kernel,
                         cudaFuncAttributeMaxDynamicSharedMemorySize, SM_BYTES);

    prep_kernel<<<Tn + 64 + 32 + 1, 256>>>(W1, topic_emb, W2);
    pool_kernel<<<dim3(Dsz / 256, Ssz, Bsz * 4), 256>>>(batch, seg_len);
    enc_kernel<<<dim3(Bsz, 24), 128>>>(seg_len, concept1, concept2,
                                       W_enc, Wc1, Wc2);
    small2_kernel<<<Bsz, 1024>>>(b_enc, Wt1, bt1, Wt2, bt2, W3);
    gemm_tc_kernel<<<Mrows / 128, 512, SM_BYTES>>>(batch, b1, w_out, b_out,
                                                   out, out_size);
}

// round 13
// speedup vs baseline: 1.3719x; 1.0527x over previous
#include <cuda_runtime.h>
#include <cuda_fp16.h>
#include <stdint.h>

// Problem constants
#define Bsz 8
#define Ssz 20
#define Fsz 200
#define Dsz 2048
#define Tn  20
#define En  128
#define Hn  128
#define CDn 300
#define THn 128
#define Mrows (Bsz*Ssz*Fsz)     // 32000
#define ROWS_PER_B (Ssz*Fsz)    // 4000

// Scratch (no allocations allowed)
__device__ float g_pool[Bsz*Dsz];
__device__ float g_venc[Bsz*Hn];                  // pooled@W_enc + concept terms
__device__ float g_vw3[Bsz*Hn];
__device__ float g_probs[Bsz*Tn];
__device__ float g_contrib[Tn*Hn];
__device__ __half g_Wh[Hn*Dsz];                   // W1^T fp16  [n][k]

// ---------------------------------------------------------------------------
__device__ __forceinline__ uint32_t smem_u32(const void* p) {
    uint32_t a;
    asm("{ .reg .u64 t; cvta.to.shared.u64 t, %1; cvt.u32.u64 %0, t; }"
        : "=r"(a) : "l"(p));
    return a;
}
__device__ __forceinline__ void mma16816h(float* d, const uint32_t* a, const uint32_t* b) {
    asm volatile(
        "mma.sync.aligned.m16n8k16.row.col.f32.f16.f16.f32 "
        "{%0,%1,%2,%3}, {%4,%5,%6,%7}, {%8,%9}, {%0,%1,%2,%3};"
        : "+f"(d[0]), "+f"(d[1]), "+f"(d[2]), "+f"(d[3])
        : "r"(a[0]), "r"(a[1]), "r"(a[2]), "r"(a[3]), "r"(b[0]), "r"(b[1]));
}
#define LDSM4(r0, r1, r2, r3, addr) \
    asm volatile("ldmatrix.sync.aligned.m8n8.x4.shared.b16 {%0,%1,%2,%3}, [%4];" \
                 : "=r"(r0), "=r"(r1), "=r"(r2), "=r"(r3) : "r"(addr))
#define CP_ASYNC16(dst, src) \
    asm volatile("cp.async.cg.shared.global [%0], [%1], 16;" :: "r"(dst), "l"(src))
#define CP_COMMIT() asm volatile("cp.async.commit_group;")
#define CP_WAIT3()  asm volatile("cp.async.wait_group 3;")
#define CP_WAIT2()  asm volatile("cp.async.wait_group 2;")
#define CP_WAIT1()  asm volatile("cp.async.wait_group 1;")
#define CP_WAIT0()  asm volatile("cp.async.wait_group 0;")

__device__ __forceinline__ uint32_t packh2(__half a, __half b) {
    __half2 h = __halves2half2(a, b);
    return *(uint32_t*)&h;
}

// ---------------------------------------------------------------------------
// prep: contrib (0..19) + zero g_pool (20..83) + W1 transpose (84..115)
// + zero g_venc (116).  grid 117 x 256
// ---------------------------------------------------------------------------
__global__ void prep_kernel(const float* __restrict__ W1,
                            const float* __restrict__ topic_emb,
                            const float* __restrict__ W2) {
    int bx = blockIdx.x, tid = threadIdx.x;
    if (bx < Tn) {
        __shared__ float red[2][Hn];
        int h = tid & 127, e2 = tid >> 7;
        float acc = 0.f;
        int e0 = e2 * 64;
        #pragma unroll 8
        for (int e = e0; e < e0 + 64; e++)
            acc += topic_emb[bx * En + e] * W2[e * Hn + h];
        red[e2][h] = acc;
        __syncthreads();
        if (e2 == 0) g_contrib[bx * Hn + h] = red[0][h] + red[1][h];
    } else if (bx < Tn + 64) {
        g_pool[(bx - Tn) * 256 + tid] = 0.f;
    } else if (bx < Tn + 96) {
        // coalesced transpose: 64 k-rows x 128 n per block
        __shared__ __half tile[64][132];
        int k0 = (bx - Tn - 64) * 64;
        #pragma unroll
        for (int p = 0; p < 8; p++) {
            int fidx = p * 256 + tid;
            int row = fidx >> 5, c4 = (fidx & 31) * 4;
            float4 v = *(const float4*)(W1 + (size_t)(k0 + row) * Hn + c4);
            tile[row][c4]     = __float2half_rn(v.x);
            tile[row][c4 + 1] = __float2half_rn(v.y);
            tile[row][c4 + 2] = __float2half_rn(v.z);
            tile[row][c4 + 3] = __float2half_rn(v.w);
        }
        __syncthreads();
        int n = tid >> 1, kh = (tid & 1) * 32;
        __half* dst = g_Wh + (size_t)n * Dsz + k0 + kh;
        uint32_t w[16];
        #pragma unroll
        for (int j = 0; j < 16; j++)
            w[j] = packh2(tile[kh + 2 * j][n], tile[kh + 2 * j + 1][n]);
        #pragma unroll
        for (int j = 0; j < 4; j++)
            *(uint4*)(dst + 8 * j) = make_uint4(w[4 * j], w[4 * j + 1],
                                                w[4 * j + 2], w[4 * j + 3]);
    } else {
        #pragma unroll
        for (int j = 0; j < 4; j++)
            g_venc[j * 256 + tid] = 0.f;
    }
}

// grid (8, 20, 32): z = b*4 + f-quarter, 256 threads (fp32 batch)
__global__ void pool_kernel(const float* __restrict__ batch,
                            const int* __restrict__ seg_len) {
    int b = blockIdx.z >> 2, fq = blockIdx.z & 3, s = blockIdx.y;
    int d = blockIdx.x * 256 + threadIdx.x;
    int len = seg_len[b * Ssz + s];
    int f0 = fq * 50;
    int f1 = min(len, f0 + 50);
    if (f0 >= f1) return;
    const float* p = batch + ((size_t)(b * Ssz + s)) * Fsz * Dsz + d;
    float acc = 0.f;
    #pragma unroll 5
    for (int f = f0; f < f1; f++) acc += p[(size_t)f * Dsz];
    atomicAdd(&g_pool[b * Dsz + d], acc);
}

// grid (Bsz, 24), 128 threads: K-split encoder + concept matvecs -> g_venc
__global__ void enc_kernel(const int* __restrict__ seg_len,
                           const float* __restrict__ concept1,
                           const float* __restrict__ concept2,
                           const float* __restrict__ W_enc,
                           const float* __restrict__ Wc1,
                           const float* __restrict__ Wc2) {
    int b = blockIdx.x, sl = blockIdx.y, h = threadIdx.x;
    float acc = 0.f;
    if (sl < 16) {
        int cnt = 0;
        #pragma unroll
        for (int s = 0; s < Ssz; s++) cnt += seg_len[b * Ssz + s];
        float inv = 1.f / fmaxf((float)cnt, 1.f);
        int d0 = sl * 128;
        #pragma unroll 8
        for (int i = 0; i < 128; i++)
            acc += g_pool[b * Dsz + d0 + i] * W_enc[(size_t)(d0 + i) * Hn + h];
        acc *= inv;
    } else {
        int c0 = (sl - 16) * 38;
        int c1 = min(c0 + 38, CDn);
        #pragma unroll 4
        for (int c = c0; c < c1; c++)
            acc += concept1[b * CDn + c] * Wc1[c * Hn + h]
                 + concept2[b * CDn + c] * Wc2[c * Hn + h];
    }
    atomicAdd(&g_venc[b * Hn + h], acc);
}

// grid Bsz blocks, 1024 threads: relu + topic net + vw3 + softmax
__global__ void small2_kernel(const float* __restrict__ b_enc,
                              const float* __restrict__ Wt1,
                              const float* __restrict__ bt1,
                              const float* __restrict__ Wt2,
                              const float* __restrict__ bt2,
                              const float* __restrict__ W3) {
    int b = blockIdx.x;
    int tid = threadIdx.x;
    int h  = tid & 127;
    int sl = tid >> 7;
    __shared__ float part[8][Hn];
    __shared__ float part2[8][Hn];
    __shared__ float video[Hn];
    __shared__ float th[THn];
    __shared__ float logits[Tn];

    // hoisted weight loads (independent of video)
    int k0 = sl * 16;
    float wt1r[16], w3r[16];
    #pragma unroll
    for (int i = 0; i < 16; i++) {
        wt1r[i] = Wt1[(k0 + i) * THn + h];
        w3r[i]  = W3[(k0 + i) * Hn + h];
    }

    if (sl == 0) video[h] = fmaxf(g_venc[b * Hn + h] + b_enc[h], 0.f);
    __syncthreads();
    {
        float a2 = 0.f, a3 = 0.f;
        #pragma unroll
        for (int i = 0; i < 16; i++) {
            float v = video[k0 + i];
            a2 += v * wt1r[i];
            a3 += v * w3r[i];
        }
        part[sl][h] = a2;
        part2[sl][h] = a3;
    }
    __syncthreads();
    if (sl == 0) {
        float a2 = bt1[h], a3 = 0.f;
        #pragma unroll
        for (int j = 0; j < 8; j++) { a2 += part[j][h]; a3 += part2[j][h]; }
        th[h] = fmaxf(a2, 0.f);
        g_vw3[b * Hn + h] = a3;
    }
    __syncthreads();
    if (tid < Tn) {
        float a4 = bt2[tid];
        #pragma unroll 8
        for (int k = 0; k < THn; k++) a4 += th[k] * Wt2[k * Tn + tid];
        logits[tid] = a4;
    }
    __syncthreads();
    if (tid == 0) {
        float m = -1e30f;
        for (int t = 0; t < Tn; t++) m = fmaxf(m, logits[t]);
        float ssum = 0.f;
        for (int t = 0; t < Tn; t++) { float e = __expf(logits[t] - m); logits[t] = e; ssum += e; }
        float invs = 1.f / ssum;
        for (int t = 0; t < Tn; t++) g_probs[b * Tn + t] = logits[t] * invs;
    }
}

// ---------------------------------------------------------------------------
// single-fp16 GEMM (batch @ W1) + fused topic epilogue.
// BM=128, BN=128, KCH=64, 512 threads (16 warps, 32x32 warp tiles).
// SINGLE barrier per chunk: A double-buffered, B 5-stage cp.async ring
// (issue-after-barrier eliminates the post-compute barrier).
// ---------------------------------------------------------------------------
#define KCH   64
#define NCHK  (Dsz / KCH)               // 32
#define STAGE_A 16384                   // A stages at 0, 16384
#define OFF_B   32768                   // B ring base (5 x 16384)
#define BSTG    16384
#define SM_CONTRIB 114688               // 10240 B
#define SM_VW3     124928               // 4096 B
#define SM_B1      129024               // 512 B
#define SM_WOUT    129536               // 512 B
#define SM_PROBS   130048               // 768 B
#define SM_RED     130816               // 8192 B  [128][4][4]
#define SM_BYTES   (139008 + 1024)

__global__ __launch_bounds__(512, 1)
void gemm_tc_kernel(const float* __restrict__ batch,
                    const float* __restrict__ b1,
                    const float* __restrict__ w_out,
                    const float* __restrict__ b_out_p,
                    float* __restrict__ out,
                    int out_size) {
    extern __shared__ char smem_raw[];
    uint32_t sb0 = smem_u32(smem_raw);
    uint32_t sb = (sb0 + 1023) & ~1023u;
    char* smem = smem_raw + (sb - sb0);

    int tid = threadIdx.x;
    int wid = tid >> 5, lane = tid & 31;
    int m0 = blockIdx.x * 128;

    // epilogue-constant preload (covered by first in-loop __syncthreads)
    for (int i = tid; i < Tn * Hn; i += 512)
        ((float*)(smem + SM_CONTRIB))[i] = g_contrib[i];
    for (int i = tid; i < Bsz * Hn; i += 512)
        ((float*)(smem + SM_VW3))[i] = g_vw3[i];
    if (tid < Hn) {
        ((float*)(smem + SM_B1))[tid] = b1[tid];
        ((float*)(smem + SM_WOUT))[tid] = w_out[tid];
    }
    if (tid < Bsz * Tn)
        ((float*)(smem + SM_PROBS))[tid] = g_probs[tid];

    // ---- per-thread A-load mapping: row = tid>>2, 16 floats at (tid&3)*16 ----
    int lrow = tid >> 2;
    int lq = tid & 3;
    const float* aptr = batch + (size_t)(m0 + lrow) * Dsz + lq * 16;
    uint32_t a_sts[2];
    #pragma unroll
    for (int g = 0; g < 2; g++)
        a_sts[g] = (uint32_t)lrow * 128 +
                   (((uint32_t)(lq * 32 + g * 16)) ^ (((uint32_t)lrow & 7) << 4));
    // B cp.async: 2 x 16B per thread per chunk
    int brow_g[2], bc16[2];
    uint32_t b_dst[2];
    #pragma unroll
    for (int j = 0; j < 2; j++) {
        int gid = tid + j * 512;
        brow_g[j] = gid >> 3;
        bc16[j] = gid & 7;
        b_dst[j] = (uint32_t)brow_g[j] * 128 +
                   (((uint32_t)(bc16[j] * 16)) ^ (((uint32_t)brow_g[j] & 7) << 4));
    }

    // ---- per-warp fragment mapping: 16 warps, warp tile 32x32 ----
    int wm = wid >> 2, wn = wid & 3;
    int lr = lane & 7, s1 = (lane >> 3) & 1, s2 = lane >> 4;
    uint32_t a_base[2], a_xor[2];
    #pragma unroll
    for (int mt = 0; mt < 2; mt++) {
        int arow = wm * 32 + mt * 16 + s1 * 8 + lr;
        a_base[mt] = (uint32_t)arow * 128;
        a_xor[mt] = ((uint32_t)arow & 7) << 4;
    }
    uint32_t b_base[2], b_xor[2];
    #pragma unroll
    for (int np = 0; np < 2; np++) {
        int brow = wn * 32 + np * 16 + s2 * 8 + lr;
        b_base[np] = (uint32_t)brow * 128;
        b_xor[np] = ((uint32_t)brow & 7) << 4;
    }
    uint32_t a_kadd = (uint32_t)(s2 * 16);
    uint32_t b_kadd = (uint32_t)(s1 * 16);

    float acc[2][4][4];
    #pragma unroll
    for (int mt = 0; mt < 2; mt++)
        #pragma unroll
        for (int nt = 0; nt < 4; nt++)
            #pragma unroll
            for (int e = 0; e < 4; e++) acc[mt][nt][e] = 0.f;

    // ---- prologue: LDG A chunk0 ; cp.async B chunks 0..3 into ring 0..3 ----
    float4 ar[4];
    #pragma unroll
    for (int g = 0; g < 4; g++) ar[g] = ((const float4*)aptr)[g];
    #pragma unroll
    for (int c = 0; c < 4; c++) {
        uint32_t bB = sb + OFF_B + c * BSTG;
        int k0 = c * KCH;
        #pragma unroll
        for (int j = 0; j < 2; j++)
            CP_ASYNC16(bB + b_dst[j],
                       g_Wh + (size_t)brow_g[j] * Dsz + k0 + bc16[j] * 8);
        CP_COMMIT();
    }

    int bs = 0;     // B ring stage of chunk c
    int bs4 = 4;    // B ring stage of chunk c+4
    for (int c = 0; c < NCHK; c++) {
        int p = c & 1;
        // B(c) must be complete: allow pending = remaining in-flight groups
        if (c <= 28)      { CP_WAIT3(); }
        else if (c == 29) { CP_WAIT2(); }
        else if (c == 30) { CP_WAIT1(); }
        else              { CP_WAIT0(); }

        // STS A chunk c (fp32 -> fp16); safe: bar(c-1) ordered compute(c-2)
        {
            char* bah = smem + p * STAGE_A;
            uint32_t hi[4];
            #pragma unroll
            for (int g = 0; g < 2; g++) {
                float4 v0 = ar[2 * g], v1 = ar[2 * g + 1];
                hi[0] = packh2(__float2half_rn(v0.x), __float2half_rn(v0.y));
                hi[1] = packh2(__float2half_rn(v0.z), __float2half_rn(v0.w));
                hi[2] = packh2(__float2half_rn(v1.x), __float2half_rn(v1.y));
                hi[3] = packh2(__float2half_rn(v1.z), __float2half_rn(v1.w));
                *(uint4*)(bah + a_sts[g]) = make_uint4(hi[0], hi[1], hi[2], hi[3]);
            }
        }
        __syncthreads();   // the ONLY barrier per chunk

        // issue B(c+4) into ring stage bs4 (last read at compute(c-1): done)
        if (c + 4 < NCHK) {
            uint32_t bB = sb + OFF_B + bs4 * BSTG;
            int k0 = (c + 4) * KCH;
            #pragma unroll
            for (int j = 0; j < 2; j++)
                CP_ASYNC16(bB + b_dst[j],
                           g_Wh + (size_t)brow_g[j] * Dsz + k0 + bc16[j] * 8);
            CP_COMMIT();
        }

        // prefetch next A chunk
        if (c + 1 < NCHK) {
            const float4* ap = (const float4*)(aptr + (c + 1) * KCH);
            #pragma unroll
            for (int g = 0; g < 4; g++) ar[g] = ap[g];
        }

        // compute on A stage p, B ring stage bs: 4 k16 steps
        {
            uint32_t Ahb = sb + p * STAGE_A;
            uint32_t Bb  = sb + OFF_B + bs * BSTG;
            #pragma unroll
            for (int ks = 0; ks < 4; ks++) {
                uint32_t ka = (uint32_t)(ks * 32) + a_kadd;
                uint32_t kb = (uint32_t)(ks * 32) + b_kadd;
                uint32_t af[2][4];
                #pragma unroll
                for (int mt = 0; mt < 2; mt++)
                    LDSM4(af[mt][0], af[mt][1], af[mt][2], af[mt][3],
                          Ahb + a_base[mt] + (ka ^ a_xor[mt]));
                uint32_t bf[4][2];
                #pragma unroll
                for (int np = 0; np < 2; np++)
                    LDSM4(bf[2 * np][0], bf[2 * np][1], bf[2 * np + 1][0], bf[2 * np + 1][1],
                          Bb + b_base[np] + (kb ^ b_xor[np]));
                #pragma unroll
                for (int mt = 0; mt < 2; mt++)
                    #pragma unroll
                    for (int nt = 0; nt < 4; nt++)
                        mma16816h(acc[mt][nt], af[mt], bf[nt]);
            }
        }

        bs  = (bs == 4)  ? 0 : bs + 1;
        bs4 = (bs4 == 4) ? 0 : bs4 + 1;
    }
    __syncthreads();   // compute done before epilogue reuses smem views

    // ----- Epilogue: base = acc + b1 + vw3[b]; 20-topic loop, 4/sync -----
    float* s_red   = (float*)(smem + SM_RED);          // [128][4][4]
    const float* s_vw3  = (const float*)(smem + SM_VW3);
    const float* s_b1v  = (const float*)(smem + SM_B1);
    const float* s_wo   = (const float*)(smem + SM_WOUT);
    const float* s_prob = (const float*)(smem + SM_PROBS);
    const float* s_con  = (const float*)(smem + SM_CONTRIB);
    float bo = b_out_p[0];
    int r = lane >> 2, q = lane & 3;

    #pragma unroll
    for (int mt = 0; mt < 2; mt++) {
        int rg0 = m0 + wm * 32 + mt * 16 + r;
        int rg1 = rg0 + 8;
        int b0 = rg0 / ROWS_PER_B;
        int b1i = rg1 / ROWS_PER_B;
        #pragma unroll
        for (int nt = 0; nt < 4; nt++)
            #pragma unroll
            for (int e = 0; e < 2; e++) {
                int col = wn * 32 + nt * 8 + 2 * q + e;
                acc[mt][nt][e]     += s_b1v[col] + s_vw3[b0 * Hn + col];
                acc[mt][nt][2 + e] += s_b1v[col] + s_vw3[b1i * Hn + col];
            }
    }

    float wv[4][2];
    #pragma unroll
    for (int nt = 0; nt < 4; nt++)
        #pragma unroll
        for (int e = 0; e < 2; e++)
            wv[nt][e] = s_wo[wn * 32 + nt * 8 + 2 * q + e];

    float orow = 0.f;     // per-row accumulator for threads tid<128
    int myrow = m0 + (tid & 127);
    int myb = myrow / ROWS_PER_B;

    for (int tg = 0; tg < 5; tg++) {
        #pragma unroll
        for (int mt = 0; mt < 2; mt++) {
            float p0[4] = {0.f, 0.f, 0.f, 0.f};
            float p1[4] = {0.f, 0.f, 0.f, 0.f};
            #pragma unroll
            for (int tt = 0; tt < 4; tt++) {
                int t = tg * 4 + tt;
                #pragma unroll
                for (int nt = 0; nt < 4; nt++)
                    #pragma unroll
                    for (int e = 0; e < 2; e++) {
                        float cv = s_con[t * Hn + wn * 32 + nt * 8 + 2 * q + e];
                        p0[tt] = fmaf(fmaxf(acc[mt][nt][e]     + cv, 0.f), wv[nt][e], p0[tt]);
                        p1[tt] = fmaf(fmaxf(acc[mt][nt][2 + e] + cv, 0.f), wv[nt][e], p1[tt]);
                    }
            }
            #pragma unroll
            for (int tt = 0; tt < 4; tt++) {
                p0[tt] += __shfl_xor_sync(0xffffffffu, p0[tt], 1);
                p0[tt] += __shfl_xor_sync(0xffffffffu, p0[tt], 2);
                p1[tt] += __shfl_xor_sync(0xffffffffu, p1[tt], 1);
                p1[tt] += __shfl_xor_sync(0xffffffffu, p1[tt], 2);
            }
            if (q == 0) {
                int row0 = wm * 32 + mt * 16 + r;
                #pragma unroll
                for (int tt = 0; tt < 4; tt++) {
                    s_red[(row0 * 4 + wn) * 4 + tt]       = p0[tt];
                    s_red[((row0 + 8) * 4 + wn) * 4 + tt] = p1[tt];
                }
            }
        }
        __syncthreads();
        if (tid < 128) {
            #pragma unroll
            for (int tt = 0; tt < 4; tt++) {
                int t = tg * 4 + tt;
                float s = s_red[(tid * 4 + 0) * 4 + tt] + s_red[(tid * 4 + 1) * 4 + tt]
                        + s_red[(tid * 4 + 2) * 4 + tt] + s_red[(tid * 4 + 3) * 4 + tt] + bo;
                float sig = 1.f / (1.f + __expf(-s));
                float sc = sig * s_prob[myb * Tn + t] - 0.01f;
                orow += fmaxf(sc, 0.f);
            }
        }
        __syncthreads();
    }

    if (tid < 128) {
        float v = orow * (1.f / (float)Tn);
        out[myrow] = v;
        if (out_size >= 2 * Mrows) out[Mrows + myrow] = v;
    }
}

// ---------------------------------------------------------------------------
extern "C" void kernel_launch(void* const* d_in, const int* in_sizes, int n_in,
                              void* d_out, int out_size) {
    const float* batch     = (const float*)d_in[0];
    const int*   seg_len   = (const int*)  d_in[1];
    const float* concept1  = (const float*)d_in[2];
    const float* concept2  = (const float*)d_in[3];
    const float* W_enc     = (const float*)d_in[4];
    const float* b_enc     = (const float*)d_in[5];
    const float* Wc1       = (const float*)d_in[6];
    const float* Wc2       = (const float*)d_in[7];
    const float* Wt1       = (const float*)d_in[8];
    const float* bt1       = (const float*)d_in[9];
    const float* Wt2       = (const float*)d_in[10];
    const float* bt2       = (const float*)d_in[11];
    const float* topic_emb = (const float*)d_in[12];
    const float* W1        = (const float*)d_in[13];
    const float* b1        = (const float*)d_in[14];
    const float* W2        = (const float*)d_in[15];
    const float* W3        = (const float*)d_in[16];
    const float* w_out     = (const float*)d_in[17];
    const float* b_out     = (const float*)d_in[18];
    float* out = (float*)d_out;

    cudaFuncSetAttribute(gemm_tc_kernel,
                         cudaFuncAttributeMaxDynamicSharedMemorySize, SM_BYTES);

    prep_kernel<<<Tn + 64 + 32 + 1, 256>>>(W1, topic_emb, W2);
    pool_kernel<<<dim3(Dsz / 256, Ssz, Bsz * 4), 256>>>(batch, seg_len);
    enc_kernel<<<dim3(Bsz, 24), 128>>>(seg_len, concept1, concept2,
                                       W_enc, Wc1, Wc2);
    small2_kernel<<<Bsz, 1024>>>(b_enc, Wt1, bt1, Wt2, bt2, W3);
    gemm_tc_kernel<<<Mrows / 128, 512, SM_BYTES>>>(batch, b1, w_out, b_out,
                                                   out, out_size);
}

// round 14
// speedup vs baseline: 1.5542x; 1.1329x over previous
#include <cuda_runtime.h>
#include <cuda_fp16.h>
#include <stdint.h>

// Problem constants
#define Bsz 8
#define Ssz 20
#define Fsz 200
#define Dsz 2048
#define Tn  20
#define En  128
#define Hn  128
#define CDn 300
#define THn 128
#define Mrows (Bsz*Ssz*Fsz)     // 32000
#define ROWS_PER_B (Ssz*Fsz)    // 4000

// Scratch (no allocations allowed)
__device__ float g_pool[Bsz*Dsz];
__device__ float g_venc[Bsz*Hn];
__device__ float g_vw3[Bsz*Hn];
__device__ float g_probs[Bsz*Tn];
__device__ float g_contrib[Tn*Hn];
__device__ __half g_Wh[Hn*Dsz];                   // W1^T fp16  [n][k]

// ---------------------------------------------------------------------------
__device__ __forceinline__ uint32_t smem_u32(const void* p) {
    uint32_t a;
    asm("{ .reg .u64 t; cvta.to.shared.u64 t, %1; cvt.u32.u64 %0, t; }"
        : "=r"(a) : "l"(p));
    return a;
}
__device__ __forceinline__ void mma16816h(float* d, const uint32_t* a, const uint32_t* b) {
    asm volatile(
        "mma.sync.aligned.m16n8k16.row.col.f32.f16.f16.f32 "
        "{%0,%1,%2,%3}, {%4,%5,%6,%7}, {%8,%9}, {%0,%1,%2,%3};"
        : "+f"(d[0]), "+f"(d[1]), "+f"(d[2]), "+f"(d[3])
        : "r"(a[0]), "r"(a[1]), "r"(a[2]), "r"(a[3]), "r"(b[0]), "r"(b[1]));
}
#define LDSM4(r0, r1, r2, r3, addr) \
    asm volatile("ldmatrix.sync.aligned.m8n8.x4.shared.b16 {%0,%1,%2,%3}, [%4];" \
                 : "=r"(r0), "=r"(r1), "=r"(r2), "=r"(r3) : "r"(addr))
#define CP_ASYNC16(dst, src) \
    asm volatile("cp.async.cg.shared.global [%0], [%1], 16;" :: "r"(dst), "l"(src))
#define CP_COMMIT() asm volatile("cp.async.commit_group;")
#define CP_WAIT3()  asm volatile("cp.async.wait_group 3;")
#define CP_WAIT2()  asm volatile("cp.async.wait_group 2;")
#define CP_WAIT1()  asm volatile("cp.async.wait_group 1;")
#define CP_WAIT0()  asm volatile("cp.async.wait_group 0;")

__device__ __forceinline__ uint32_t packh2(__half a, __half b) {
    __half2 h = __halves2half2(a, b);
    return *(uint32_t*)&h;
}

// ---------------------------------------------------------------------------
// prep: contrib (0..19) + zero g_pool (20..83) + W1 transpose (84..115)
// + zero g_venc (116).  grid 117 x 256
// ---------------------------------------------------------------------------
__global__ void prep_kernel(const float* __restrict__ W1,
                            const float* __restrict__ topic_emb,
                            const float* __restrict__ W2) {
    int bx = blockIdx.x, tid = threadIdx.x;
    if (bx < Tn) {
        __shared__ float red[2][Hn];
        int h = tid & 127, e2 = tid >> 7;
        float acc = 0.f;
        int e0 = e2 * 64;
        #pragma unroll 8
        for (int e = e0; e < e0 + 64; e++)
            acc += topic_emb[bx * En + e] * W2[e * Hn + h];
        red[e2][h] = acc;
        __syncthreads();
        if (e2 == 0) g_contrib[bx * Hn + h] = red[0][h] + red[1][h];
    } else if (bx < Tn + 64) {
        g_pool[(bx - Tn) * 256 + tid] = 0.f;
    } else if (bx < Tn + 96) {
        __shared__ __half tile[64][132];
        int k0 = (bx - Tn - 64) * 64;
        #pragma unroll
        for (int p = 0; p < 8; p++) {
            int fidx = p * 256 + tid;
            int row = fidx >> 5, c4 = (fidx & 31) * 4;
            float4 v = *(const float4*)(W1 + (size_t)(k0 + row) * Hn + c4);
            tile[row][c4]     = __float2half_rn(v.x);
            tile[row][c4 + 1] = __float2half_rn(v.y);
            tile[row][c4 + 2] = __float2half_rn(v.z);
            tile[row][c4 + 3] = __float2half_rn(v.w);
        }
        __syncthreads();
        int n = tid >> 1, kh = (tid & 1) * 32;
        __half* dst = g_Wh + (size_t)n * Dsz + k0 + kh;
        uint32_t w[16];
        #pragma unroll
        for (int j = 0; j < 16; j++)
            w[j] = packh2(tile[kh + 2 * j][n], tile[kh + 2 * j + 1][n]);
        #pragma unroll
        for (int j = 0; j < 4; j++)
            *(uint4*)(dst + 8 * j) = make_uint4(w[4 * j], w[4 * j + 1],
                                                w[4 * j + 2], w[4 * j + 3]);
    } else {
        #pragma unroll
        for (int j = 0; j < 4; j++)
            g_venc[j * 256 + tid] = 0.f;
    }
}

// grid (8, 20, 32): z = b*4 + f-quarter, 256 threads (fp32 batch)
__global__ void pool_kernel(const float* __restrict__ batch,
                            const int* __restrict__ seg_len) {
    int b = blockIdx.z >> 2, fq = blockIdx.z & 3, s = blockIdx.y;
    int d = blockIdx.x * 256 + threadIdx.x;
    int len = seg_len[b * Ssz + s];
    int f0 = fq * 50;
    int f1 = min(len, f0 + 50);
    if (f0 >= f1) return;
    const float* p = batch + ((size_t)(b * Ssz + s)) * Fsz * Dsz + d;
    float acc = 0.f;
    #pragma unroll 5
    for (int f = f0; f < f1; f++) acc += p[(size_t)f * Dsz];
    atomicAdd(&g_pool[b * Dsz + d], acc);
}

// grid (Bsz, 24), 128 threads: K-split encoder + concept matvecs -> g_venc
__global__ void enc_kernel(const int* __restrict__ seg_len,
                           const float* __restrict__ concept1,
                           const float* __restrict__ concept2,
                           const float* __restrict__ W_enc,
                           const float* __restrict__ Wc1,
                           const float* __restrict__ Wc2) {
    int b = blockIdx.x, sl = blockIdx.y, h = threadIdx.x;
    float acc = 0.f;
    if (sl < 16) {
        int cnt = 0;
        #pragma unroll
        for (int s = 0; s < Ssz; s++) cnt += seg_len[b * Ssz + s];
        float inv = 1.f / fmaxf((float)cnt, 1.f);
        int d0 = sl * 128;
        #pragma unroll 8
        for (int i = 0; i < 128; i++)
            acc += g_pool[b * Dsz + d0 + i] * W_enc[(size_t)(d0 + i) * Hn + h];
        acc *= inv;
    } else {
        int c0 = (sl - 16) * 38;
        int c1 = min(c0 + 38, CDn);
        #pragma unroll 4
        for (int c = c0; c < c1; c++)
            acc += concept1[b * CDn + c] * Wc1[c * Hn + h]
                 + concept2[b * CDn + c] * Wc2[c * Hn + h];
    }
    atomicAdd(&g_venc[b * Hn + h], acc);
}

// grid Bsz blocks, 1024 threads: relu + topic net + vw3 + softmax
__global__ void small2_kernel(const float* __restrict__ b_enc,
                              const float* __restrict__ Wt1,
                              const float* __restrict__ bt1,
                              const float* __restrict__ Wt2,
                              const float* __restrict__ bt2,
                              const float* __restrict__ W3) {
    int b = blockIdx.x;
    int tid = threadIdx.x;
    int h  = tid & 127;
    int sl = tid >> 7;
    __shared__ float part[8][Hn];
    __shared__ float part2[8][Hn];
    __shared__ float video[Hn];
    __shared__ float th[THn];
    __shared__ float logits[Tn];

    int k0 = sl * 16;
    float wt1r[16], w3r[16];
    #pragma unroll
    for (int i = 0; i < 16; i++) {
        wt1r[i] = Wt1[(k0 + i) * THn + h];
        w3r[i]  = W3[(k0 + i) * Hn + h];
    }

    if (sl == 0) video[h] = fmaxf(g_venc[b * Hn + h] + b_enc[h], 0.f);
    __syncthreads();
    {
        float a2 = 0.f, a3 = 0.f;
        #pragma unroll
        for (int i = 0; i < 16; i++) {
            float v = video[k0 + i];
            a2 += v * wt1r[i];
            a3 += v * w3r[i];
        }
        part[sl][h] = a2;
        part2[sl][h] = a3;
    }
    __syncthreads();
    if (sl == 0) {
        float a2 = bt1[h], a3 = 0.f;
        #pragma unroll
        for (int j = 0; j < 8; j++) { a2 += part[j][h]; a3 += part2[j][h]; }
        th[h] = fmaxf(a2, 0.f);
        g_vw3[b * Hn + h] = a3;
    }
    __syncthreads();
    if (tid < Tn) {
        float a4 = bt2[tid];
        #pragma unroll 8
        for (int k = 0; k < THn; k++) a4 += th[k] * Wt2[k * Tn + tid];
        logits[tid] = a4;
    }
    __syncthreads();
    if (tid == 0) {
        float m = -1e30f;
        for (int t = 0; t < Tn; t++) m = fmaxf(m, logits[t]);
        float ssum = 0.f;
        for (int t = 0; t < Tn; t++) { float e = __expf(logits[t] - m); logits[t] = e; ssum += e; }
        float invs = 1.f / ssum;
        for (int t = 0; t < Tn; t++) g_probs[b * Tn + t] = logits[t] * invs;
    }
}

// ---------------------------------------------------------------------------
// single-fp16 GEMM (batch @ W1) + fused topic epilogue.
// 512 threads, 16 warps (32x32 warp tiles), single barrier per chunk.
// A: cp.async fp32 3-stage ring -> LDS -> cvt -> STS fp16 double buffer.
// B: cp.async fp16 5-stage ring. One commit group per chunk (A(c+3)+B(c+4)).
// ---------------------------------------------------------------------------
#define KCH   64
#define NCHK  (Dsz / KCH)               // 32
#define A16STG 16384                    // fp16 A stages at 0, 16384
#define OFF_A32 32768                   // fp32 A ring: 3 x 32768
#define A32STG  32768
#define OFF_B   131072                  // B ring: 5 x 16384
#define BSTG    16384
#define SM_CONTRIB 212992               // 10240 B
#define SM_VW3     223232               // 4096 B
#define SM_B1      227328               // 512 B
#define SM_WOUT    227840               // 512 B
#define SM_PROBS   228352               // 768 B
#define SM_RED     32768                // 8192 B, overlays A32 ring (post-loop)
#define SM_BYTES   (229120 + 1024)

__global__ __launch_bounds__(512, 1)
void gemm_tc_kernel(const float* __restrict__ batch,
                    const float* __restrict__ b1,
                    const float* __restrict__ w_out,
                    const float* __restrict__ b_out_p,
                    float* __restrict__ out,
                    int out_size) {
    extern __shared__ char smem_raw[];
    uint32_t sb0 = smem_u32(smem_raw);
    uint32_t sb = (sb0 + 1023) & ~1023u;
    char* smem = smem_raw + (sb - sb0);

    int tid = threadIdx.x;
    int wid = tid >> 5, lane = tid & 31;
    int m0 = blockIdx.x * 128;

    // epilogue-constant preload (covered by first in-loop __syncthreads)
    for (int i = tid; i < Tn * Hn; i += 512)
        ((float*)(smem + SM_CONTRIB))[i] = g_contrib[i];
    for (int i = tid; i < Bsz * Hn; i += 512)
        ((float*)(smem + SM_VW3))[i] = g_vw3[i];
    if (tid < Hn) {
        ((float*)(smem + SM_B1))[tid] = b1[tid];
        ((float*)(smem + SM_WOUT))[tid] = w_out[tid];
    }
    if (tid < Bsz * Tn)
        ((float*)(smem + SM_PROBS))[tid] = g_probs[tid];

    // ---- A32 cp.async mapping: part j -> smem j*8192 + tid*16 ----
    // row = j*32 + (tid>>4), float col = (tid&15)*4
    uint32_t a32_off[4];
    const float* a32_src[4];
    int arow_c = tid >> 4;       // 0..31
    int acol_f = (tid & 15) * 4; // 0..60
    #pragma unroll
    for (int j = 0; j < 4; j++) {
        a32_off[j] = (uint32_t)(j * 8192 + tid * 16);
        a32_src[j] = batch + (size_t)(m0 + j * 32 + arow_c) * Dsz + acol_f;
    }
    // A16 STS target (per part j): row r = j*32 + arow_c, byte col = (tid&15)*8
    uint32_t a16_sts[4];
    #pragma unroll
    for (int j = 0; j < 4; j++) {
        uint32_t r = (uint32_t)(j * 32 + arow_c);
        uint32_t cb = (uint32_t)((tid & 15) * 8);
        a16_sts[j] = r * 128 + (cb ^ ((r & 7) << 4));
    }

    // B cp.async: 2 x 16B per thread per chunk
    int brow_g[2], bc16[2];
    uint32_t b_dst[2];
    #pragma unroll
    for (int j = 0; j < 2; j++) {
        int gid = tid + j * 512;
        brow_g[j] = gid >> 3;
        bc16[j] = gid & 7;
        b_dst[j] = (uint32_t)brow_g[j] * 128 +
                   (((uint32_t)(bc16[j] * 16)) ^ (((uint32_t)brow_g[j] & 7) << 4));
    }

    // ---- per-warp fragment mapping: 16 warps, warp tile 32x32 ----
    int wm = wid >> 2, wn = wid & 3;
    int lr = lane & 7, s1 = (lane >> 3) & 1, s2 = lane >> 4;
    uint32_t a_base[2], a_xor[2];
    #pragma unroll
    for (int mt = 0; mt < 2; mt++) {
        int arow = wm * 32 + mt * 16 + s1 * 8 + lr;
        a_base[mt] = (uint32_t)arow * 128;
        a_xor[mt] = ((uint32_t)arow & 7) << 4;
    }
    uint32_t b_base[2], b_xor[2];
    #pragma unroll
    for (int np = 0; np < 2; np++) {
        int brow = wn * 32 + np * 16 + s2 * 8 + lr;
        b_base[np] = (uint32_t)brow * 128;
        b_xor[np] = ((uint32_t)brow & 7) << 4;
    }
    uint32_t a_kadd = (uint32_t)(s2 * 16);
    uint32_t b_kadd = (uint32_t)(s1 * 16);

    float acc[2][4][4];
    #pragma unroll
    for (int mt = 0; mt < 2; mt++)
        #pragma unroll
        for (int nt = 0; nt < 4; nt++)
            #pragma unroll
            for (int e = 0; e < 4; e++) acc[mt][nt][e] = 0.f;

    // ---- prologue: groups g0..g3 ----
    // g_c (c=0..2): A32(c) -> a32 ring c, B(c) -> b ring c.  g3: B(3) only.
    #pragma unroll
    for (int c = 0; c < 3; c++) {
        uint32_t aB = sb + OFF_A32 + c * A32STG;
        uint32_t bB = sb + OFF_B + c * BSTG;
        int k0 = c * KCH;
        #pragma unroll
        for (int j = 0; j < 4; j++)
            CP_ASYNC16(aB + a32_off[j], a32_src[j] + k0);
        #pragma unroll
        for (int j = 0; j < 2; j++)
            CP_ASYNC16(bB + b_dst[j],
                       g_Wh + (size_t)brow_g[j] * Dsz + k0 + bc16[j] * 8);
        CP_COMMIT();
    }
    {
        uint32_t bB = sb + OFF_B + 3 * BSTG;
        #pragma unroll
        for (int j = 0; j < 2; j++)
            CP_ASYNC16(bB + b_dst[j],
                       g_Wh + (size_t)brow_g[j] * Dsz + 3 * KCH + bc16[j] * 8);
        CP_COMMIT();
    }

    int bs = 0;      // B ring stage of chunk c
    int bs4 = 4;     // B ring stage of chunk c+4
    int a3s = 0;     // A32 ring stage of chunk c (== stage of c+3 after reuse)
    for (int c = 0; c < NCHK; c++) {
        int p = c & 1;
        if (c <= 2)       { CP_WAIT3(); }
        else if (c <= 29) { CP_WAIT2(); }
        else if (c == 30) { CP_WAIT1(); }
        else              { CP_WAIT0(); }

        // LDS A32(c) -> convert -> STS A16 stage p
        {
            char* a32b = smem + OFF_A32 + a3s * A32STG;
            char* a16b = smem + p * A16STG;
            #pragma unroll
            for (int j = 0; j < 4; j++) {
                float4 v = *(const float4*)(a32b + a32_off[j]);
                uint32_t h01 = packh2(__float2half_rn(v.x), __float2half_rn(v.y));
                uint32_t h23 = packh2(__float2half_rn(v.z), __float2half_rn(v.w));
                *(uint2*)(a16b + a16_sts[j]) = make_uint2(h01, h23);
            }
        }
        __syncthreads();   // the ONLY barrier per chunk

        // issue group: A32(c+3) into ring stage a3s (just freed) + B(c+4)
        {
            bool hasA = (c + 3 < NCHK);
            bool hasB = (c + 4 < NCHK);
            if (hasA) {
                uint32_t aB = sb + OFF_A32 + a3s * A32STG;
                int k0 = (c + 3) * KCH;
                #pragma unroll
                for (int j = 0; j < 4; j++)
                    CP_ASYNC16(aB + a32_off[j], a32_src[j] + k0);
            }
            if (hasB) {
                uint32_t bB = sb + OFF_B + bs4 * BSTG;
                int k0 = (c + 4) * KCH;
                #pragma unroll
                for (int j = 0; j < 2; j++)
                    CP_ASYNC16(bB + b_dst[j],
                               g_Wh + (size_t)brow_g[j] * Dsz + k0 + bc16[j] * 8);
            }
            if (hasA || hasB) CP_COMMIT();
        }

        // compute on A16 stage p, B ring stage bs: 4 k16 steps
        {
            uint32_t Ahb = sb + p * A16STG;
            uint32_t Bb  = sb + OFF_B + bs * BSTG;
            #pragma unroll
            for (int ks = 0; ks < 4; ks++) {
                uint32_t ka = (uint32_t)(ks * 32) + a_kadd;
                uint32_t kb = (uint32_t)(ks * 32) + b_kadd;
                uint32_t af[2][4];
                #pragma unroll
                for (int mt = 0; mt < 2; mt++)
                    LDSM4(af[mt][0], af[mt][1], af[mt][2], af[mt][3],
                          Ahb + a_base[mt] + (ka ^ a_xor[mt]));
                uint32_t bf[4][2];
                #pragma unroll
                for (int np = 0; np < 2; np++)
                    LDSM4(bf[2 * np][0], bf[2 * np][1], bf[2 * np + 1][0], bf[2 * np + 1][1],
                          Bb + b_base[np] + (kb ^ b_xor[np]));
                #pragma unroll
                for (int mt = 0; mt < 2; mt++)
                    #pragma unroll
                    for (int nt = 0; nt < 4; nt++)
                        mma16816h(acc[mt][nt], af[mt], bf[nt]);
            }
        }

        bs  = (bs == 4)  ? 0 : bs + 1;
        bs4 = (bs4 == 4) ? 0 : bs4 + 1;
        a3s = (a3s == 2) ? 0 : a3s + 1;
    }
    __syncthreads();   // compute done; s_red overlays A32 ring below

    // ----- Epilogue: base = acc + b1 + vw3[b]; 20-topic loop, 4/sync -----
    float* s_red   = (float*)(smem + SM_RED);          // [128][4][4]
    const float* s_vw3  = (const float*)(smem + SM_VW3);
    const float* s_b1v  = (const float*)(smem + SM_B1);
    const float* s_wo   = (const float*)(smem + SM_WOUT);
    const float* s_prob = (const float*)(smem + SM_PROBS);
    const float* s_con  = (const float*)(smem + SM_CONTRIB);
    float bo = b_out_p[0];
    int r = lane >> 2, q = lane & 3;

    #pragma unroll
    for (int mt = 0; mt < 2; mt++) {
        int rg0 = m0 + wm * 32 + mt * 16 + r;
        int rg1 = rg0 + 8;
        int b0 = rg0 / ROWS_PER_B;
        int b1i = rg1 / ROWS_PER_B;
        #pragma unroll
        for (int nt = 0; nt < 4; nt++)
            #pragma unroll
            for (int e = 0; e < 2; e++) {
                int col = wn * 32 + nt * 8 + 2 * q + e;
                acc[mt][nt][e]     += s_b1v[col] + s_vw3[b0 * Hn + col];
                acc[mt][nt][2 + e] += s_b1v[col] + s_vw3[b1i * Hn + col];
            }
    }

    float wv[4][2];
    #pragma unroll
    for (int nt = 0; nt < 4; nt++)
        #pragma unroll
        for (int e = 0; e < 2; e++)
            wv[nt][e] = s_wo[wn * 32 + nt * 8 + 2 * q + e];

    float orow = 0.f;     // per-row accumulator for threads tid<128
    int myrow = m0 + (tid & 127);
    int myb = myrow / ROWS_PER_B;

    for (int tg = 0; tg < 5; tg++) {
        #pragma unroll
        for (int mt = 0; mt < 2; mt++) {
            float p0[4] = {0.f, 0.f, 0.f, 0.f};
            float p1[4] = {0.f, 0.f, 0.f, 0.f};
            #pragma unroll
            for (int tt = 0; tt < 4; tt++) {
                int t = tg * 4 + tt;
                #pragma unroll
                for (int nt = 0; nt < 4; nt++)
                    #pragma unroll
                    for (int e = 0; e < 2; e++) {
                        float cv = s_con[t * Hn + wn * 32 + nt * 8 + 2 * q + e];
                        p0[tt] = fmaf(fmaxf(acc[mt][nt][e]     + cv, 0.f), wv[nt][e], p0[tt]);
                        p1[tt] = fmaf(fmaxf(acc[mt][nt][2 + e] + cv, 0.f), wv[nt][e], p1[tt]);
                    }
            }
            #pragma unroll
            for (int tt = 0; tt < 4; tt++) {
                p0[tt] += __shfl_xor_sync(0xffffffffu, p0[tt], 1);
                p0[tt] += __shfl_xor_sync(0xffffffffu, p0[tt], 2);
                p1[tt] += __shfl_xor_sync(0xffffffffu, p1[tt], 1);
                p1[tt] += __shfl_xor_sync(0xffffffffu, p1[tt], 2);
            }
            if (q == 0) {
                int row0 = wm * 32 + mt * 16 + r;
                #pragma unroll
                for (int tt = 0; tt < 4; tt++) {
                    s_red[(row0 * 4 + wn) * 4 + tt]       = p0[tt];
                    s_red[((row0 + 8) * 4 + wn) * 4 + tt] = p1[tt];
                }
            }
        }
        __syncthreads();
        if (tid < 128) {
            #pragma unroll
            for (int tt = 0; tt < 4; tt++) {
                int t = tg * 4 + tt;
                float s = s_red[(tid * 4 + 0) * 4 + tt] + s_red[(tid * 4 + 1) * 4 + tt]
                        + s_red[(tid * 4 + 2) * 4 + tt] + s_red[(tid * 4 + 3) * 4 + tt] + bo;
                float sig = 1.f / (1.f + __expf(-s));
                float sc = sig * s_prob[myb * Tn + t] - 0.01f;
                orow += fmaxf(sc, 0.f);
            }
        }
        __syncthreads();
    }

    if (tid < 128) {
        float v = orow * (1.f / (float)Tn);
        out[myrow] = v;
        if (out_size >= 2 * Mrows) out[Mrows + myrow] = v;
    }
}

// ---------------------------------------------------------------------------
extern "C" void kernel_launch(void* const* d_in, const int* in_sizes, int n_in,
                              void* d_out, int out_size) {
    const float* batch     = (const float*)d_in[0];
    const int*   seg_len   = (const int*)  d_in[1];
    const float* concept1  = (const float*)d_in[2];
    const float* concept2  = (const float*)d_in[3];
    const float* W_enc     = (const float*)d_in[4];
    const float* b_enc     = (const float*)d_in[5];
    const float* Wc1       = (const float*)d_in[6];
    const float* Wc2       = (const float*)d_in[7];
    const float* Wt1       = (const float*)d_in[8];
    const float* bt1       = (const float*)d_in[9];
    const float* Wt2       = (const float*)d_in[10];
    const float* bt2       = (const float*)d_in[11];
    const float* topic_emb = (const float*)d_in[12];
    const float* W1        = (const float*)d_in[13];
    const float* b1        = (const float*)d_in[14];
    const float* W2        = (const float*)d_in[15];
    const float* W3        = (const float*)d_in[16];
    const float* w_out     = (const float*)d_in[17];
    const float* b_out     = (const float*)d_in[18];
    float* out = (float*)d_out;

    cudaFuncSetAttribute(gemm_tc_kernel,
                         cudaFuncAttributeMaxDynamicSharedMemorySize, SM_BYTES);

    prep_kernel<<<Tn + 64 + 32 + 1, 256>>>(W1, topic_emb, W2);
    pool_kernel<<<dim3(Dsz / 256, Ssz, Bsz * 4), 256>>>(batch, seg_len);
    enc_kernel<<<dim3(Bsz, 24), 128>>>(seg_len, concept1, concept2,
                                       W_enc, Wc1, Wc2);
    small2_kernel<<<Bsz, 1024>>>(b_enc, Wt1, bt1, Wt2, bt2, W3);
    gemm_tc_kernel<<<Mrows / 128, 512, SM_BYTES>>>(batch, b1, w_out, b_out,
                                                   out, out_size);
}

// round 15
// speedup vs baseline: 1.6456x; 1.0588x over previous
#include <cuda_runtime.h>
#include <cuda_fp16.h>
#include <stdint.h>

// Problem constants
#define Bsz 8
#define Ssz 20
#define Fsz 200
#define Dsz 2048
#define Tn  20
#define En  128
#define Hn  128
#define CDn 300
#define THn 128
#define Mrows (Bsz*Ssz*Fsz)     // 32000
#define ROWS_PER_B (Ssz*Fsz)    // 4000

// Scratch (no allocations allowed)
__device__ float g_pool[Bsz*Dsz];
__device__ float g_venc[Bsz*Hn];
__device__ float g_vw3[Bsz*Hn];
__device__ float g_probs[Bsz*Tn];
__device__ float g_contrib[Tn*Hn];
__device__ int   g_cnt[Bsz];
__device__ __half g_Wh[Hn*Dsz];                   // W1^T fp16  [n][k]

// ---------------------------------------------------------------------------
__device__ __forceinline__ uint32_t smem_u32(const void* p) {
    uint32_t a;
    asm("{ .reg .u64 t; cvta.to.shared.u64 t, %1; cvt.u32.u64 %0, t; }"
        : "=r"(a) : "l"(p));
    return a;
}
__device__ __forceinline__ void mma16816h(float* d, const uint32_t* a, const uint32_t* b) {
    asm volatile(
        "mma.sync.aligned.m16n8k16.row.col.f32.f16.f16.f32 "
        "{%0,%1,%2,%3}, {%4,%5,%6,%7}, {%8,%9}, {%0,%1,%2,%3};"
        : "+f"(d[0]), "+f"(d[1]), "+f"(d[2]), "+f"(d[3])
        : "r"(a[0]), "r"(a[1]), "r"(a[2]), "r"(a[3]), "r"(b[0]), "r"(b[1]));
}
#define LDSM4(r0, r1, r2, r3, addr) \
    asm volatile("ldmatrix.sync.aligned.m8n8.x4.shared.b16 {%0,%1,%2,%3}, [%4];" \
                 : "=r"(r0), "=r"(r1), "=r"(r2), "=r"(r3) : "r"(addr))
#define CP_ASYNC16(dst, src) \
    asm volatile("cp.async.cg.shared.global [%0], [%1], 16;" :: "r"(dst), "l"(src))
#define CP_COMMIT() asm volatile("cp.async.commit_group;")
#define CP_WAIT3()  asm volatile("cp.async.wait_group 3;")
#define CP_WAIT2()  asm volatile("cp.async.wait_group 2;")
#define CP_WAIT1()  asm volatile("cp.async.wait_group 1;")
#define CP_WAIT0()  asm volatile("cp.async.wait_group 0;")

__device__ __forceinline__ uint32_t packh2(__half a, __half b) {
    __half2 h = __halves2half2(a, b);
    return *(uint32_t*)&h;
}

// ---------------------------------------------------------------------------
// prep: contrib (0..19) + zero g_pool (20..83) + W1 transpose (84..115)
// + zero g_venc/g_cnt (116).  grid 117 x 256
// ---------------------------------------------------------------------------
__global__ void prep_kernel(const float* __restrict__ W1,
                            const float* __restrict__ topic_emb,
                            const float* __restrict__ W2) {
    int bx = blockIdx.x, tid = threadIdx.x;
    if (bx < Tn) {
        __shared__ float red[2][Hn];
        int h = tid & 127, e2 = tid >> 7;
        float acc = 0.f;
        int e0 = e2 * 64;
        #pragma unroll 8
        for (int e = e0; e < e0 + 64; e++)
            acc += topic_emb[bx * En + e] * W2[e * Hn + h];
        red[e2][h] = acc;
        __syncthreads();
        if (e2 == 0) g_contrib[bx * Hn + h] = red[0][h] + red[1][h];
    } else if (bx < Tn + 64) {
        g_pool[(bx - Tn) * 256 + tid] = 0.f;
    } else if (bx < Tn + 96) {
        __shared__ __half tile[64][132];
        int k0 = (bx - Tn - 64) * 64;
        #pragma unroll
        for (int p = 0; p < 8; p++) {
            int fidx = p * 256 + tid;
            int row = fidx >> 5, c4 = (fidx & 31) * 4;
            float4 v = *(const float4*)(W1 + (size_t)(k0 + row) * Hn + c4);
            tile[row][c4]     = __float2half_rn(v.x);
            tile[row][c4 + 1] = __float2half_rn(v.y);
            tile[row][c4 + 2] = __float2half_rn(v.z);
            tile[row][c4 + 3] = __float2half_rn(v.w);
        }
        __syncthreads();
        int n = tid >> 1, kh = (tid & 1) * 32;
        __half* dst = g_Wh + (size_t)n * Dsz + k0 + kh;
        uint32_t w[16];
        #pragma unroll
        for (int j = 0; j < 16; j++)
            w[j] = packh2(tile[kh + 2 * j][n], tile[kh + 2 * j + 1][n]);
        #pragma unroll
        for (int j = 0; j < 4; j++)
            *(uint4*)(dst + 8 * j) = make_uint4(w[4 * j], w[4 * j + 1],
                                                w[4 * j + 2], w[4 * j + 3]);
    } else {
        #pragma unroll
        for (int j = 0; j < 4; j++)
            g_venc[j * 256 + tid] = 0.f;
        if (tid < Bsz) g_cnt[tid] = 0;
    }
}

// grid (8, 20, 32): z = b*4 + f-quarter, 256 threads (fp32 batch)
__global__ void pool_kernel(const float* __restrict__ batch,
                            const int* __restrict__ seg_len) {
    int b = blockIdx.z >> 2, fq = blockIdx.z & 3, s = blockIdx.y;
    int d = blockIdx.x * 256 + threadIdx.x;
    int len = seg_len[b * Ssz + s];
    int f0 = fq * 50;
    int f1 = min(len, f0 + 50);
    if (f0 >= f1) return;
    const float* p = batch + ((size_t)(b * Ssz + s)) * Fsz * Dsz + d;
    float acc = 0.f;
    #pragma unroll 5
    for (int f = f0; f < f1; f++) acc += p[(size_t)f * Dsz];
    atomicAdd(&g_pool[b * Dsz + d], acc);
}

// ---------------------------------------------------------------------------
// encsmall: grid (Bsz, 5) x 1024.
// y=0..3: encoder d-subslices (32 total) -> g_venc, then signal g_cnt[b].
// y=4   : concept terms -> g_venc, hoist small2 weights, spin for g_cnt[b]==4,
//         then small2 body (relu + topic net + vw3 + softmax).
// ---------------------------------------------------------------------------
__global__ void encsmall_kernel(const int* __restrict__ seg_len,
                                const float* __restrict__ concept1,
                                const float* __restrict__ concept2,
                                const float* __restrict__ W_enc,
                                const float* __restrict__ Wc1,
                                const float* __restrict__ Wc2,
                                const float* __restrict__ b_enc,
                                const float* __restrict__ Wt1,
                                const float* __restrict__ bt1,
                                const float* __restrict__ Wt2,
                                const float* __restrict__ bt2,
                                const float* __restrict__ W3) {
    int b = blockIdx.x, y = blockIdx.y;
    int tid = threadIdx.x;
    int h  = tid & 127;
    int sl = tid >> 7;                 // 0..7

    if (y < 4) {
        // ---- encoder slice: subslice = y*8+sl, 64 d-iterations ----
        int cnt = 0;
        #pragma unroll
        for (int s = 0; s < Ssz; s++) cnt += seg_len[b * Ssz + s];
        float inv = 1.f / fmaxf((float)cnt, 1.f);
        int d0 = (y * 8 + sl) * 64;
        float acc = 0.f;
        #pragma unroll 8
        for (int i = 0; i < 64; i++)
            acc += g_pool[b * Dsz + d0 + i] * W_enc[(size_t)(d0 + i) * Hn + h];
        atomicAdd(&g_venc[b * Hn + h], acc * inv);
        __threadfence();
        __syncthreads();               // all block atomics issued+fenced
        if (tid == 0) atomicAdd(&g_cnt[b], 1);
        return;
    }

    // ---- y == 4: concepts + small2 ----
    __shared__ float part[8][Hn];
    __shared__ float part2[8][Hn];
    __shared__ float video[Hn];
    __shared__ float th[THn];
    __shared__ float logits[Tn];

    {
        int c0 = sl * 38;
        int c1 = min(c0 + 38, CDn);
        float acc = 0.f;
        #pragma unroll 4
        for (int c = c0; c < c1; c++)
            acc += concept1[b * CDn + c] * Wc1[c * Hn + h]
                 + concept2[b * CDn + c] * Wc2[c * Hn + h];
        atomicAdd(&g_venc[b * Hn + h], acc);
    }

    // hoisted small2 weight loads (independent of video)
    int k0 = sl * 16;
    float wt1r[16], w3r[16];
    #pragma unroll
    for (int i = 0; i < 16; i++) {
        wt1r[i] = Wt1[(k0 + i) * THn + h];
        w3r[i]  = W3[(k0 + i) * Hn + h];
    }

    // wait for all 4 encoder blocks of this b
    if (tid == 0) {
        while (atomicAdd(&g_cnt[b], 0) < 4) { }
    }
    __syncthreads();   // flag observed + own concept atomics ordered

    if (sl == 0) video[h] = fmaxf(g_venc[b * Hn + h] + b_enc[h], 0.f);
    __syncthreads();
    {
        float a2 = 0.f, a3 = 0.f;
        #pragma unroll
        for (int i = 0; i < 16; i++) {
            float v = video[k0 + i];
            a2 += v * wt1r[i];
            a3 += v * w3r[i];
        }
        part[sl][h] = a2;
        part2[sl][h] = a3;
    }
    __syncthreads();
    if (sl == 0) {
        float a2 = bt1[h], a3 = 0.f;
        #pragma unroll
        for (int j = 0; j < 8; j++) { a2 += part[j][h]; a3 += part2[j][h]; }
        th[h] = fmaxf(a2, 0.f);
        g_vw3[b * Hn + h] = a3;
    }
    __syncthreads();
    if (tid < Tn) {
        float a4 = bt2[tid];
        #pragma unroll 8
        for (int k = 0; k < THn; k++) a4 += th[k] * Wt2[k * Tn + tid];
        logits[tid] = a4;
    }
    __syncthreads();
    if (tid == 0) {
        float m = -1e30f;
        for (int t = 0; t < Tn; t++) m = fmaxf(m, logits[t]);
        float ssum = 0.f;
        for (int t = 0; t < Tn; t++) { float e = __expf(logits[t] - m); logits[t] = e; ssum += e; }
        float invs = 1.f / ssum;
        for (int t = 0; t < Tn; t++) g_probs[b * Tn + t] = logits[t] * invs;
    }
}

// ---------------------------------------------------------------------------
// single-fp16 GEMM (batch @ W1) + fused topic epilogue.
// 512 threads, 16 warps (32x32 warp tiles), single barrier per chunk.
// A: cp.async fp32 3-stage ring -> LDS -> cvt -> STS fp16 double buffer.
// B: cp.async fp16 5-stage ring. One commit group per chunk (A(c+3)+B(c+4)).
// Epilogue constants loaded AFTER the mainloop.
// ---------------------------------------------------------------------------
#define KCH   64
#define NCHK  (Dsz / KCH)               // 32
#define A16STG 16384                    // fp16 A stages at 0, 16384
#define OFF_A32 32768                   // fp32 A ring: 3 x 32768
#define A32STG  32768
#define OFF_B   131072                  // B ring: 5 x 16384
#define BSTG    16384
#define SM_CONTRIB 212992               // 10240 B
#define SM_VW3     223232               // 4096 B
#define SM_B1      227328               // 512 B
#define SM_WOUT    227840               // 512 B
#define SM_PROBS   228352               // 768 B
#define SM_RED     32768                // 8192 B, overlays A32 ring (post-loop)
#define SM_BYTES   (229120 + 1024)

__global__ __launch_bounds__(512, 1)
void gemm_tc_kernel(const float* __restrict__ batch,
                    const float* __restrict__ b1,
                    const float* __restrict__ w_out,
                    const float* __restrict__ b_out_p,
                    float* __restrict__ out,
                    int out_size) {
    extern __shared__ char smem_raw[];
    uint32_t sb0 = smem_u32(smem_raw);
    uint32_t sb = (sb0 + 1023) & ~1023u;
    char* smem = smem_raw + (sb - sb0);

    int tid = threadIdx.x;
    int wid = tid >> 5, lane = tid & 31;
    int m0 = blockIdx.x * 128;

    // ---- A32 cp.async mapping: part j -> smem j*8192 + tid*16 ----
    uint32_t a32_off[4];
    const float* a32_src[4];
    int arow_c = tid >> 4;       // 0..31
    int acol_f = (tid & 15) * 4; // 0..60
    #pragma unroll
    for (int j = 0; j < 4; j++) {
        a32_off[j] = (uint32_t)(j * 8192 + tid * 16);
        a32_src[j] = batch + (size_t)(m0 + j * 32 + arow_c) * Dsz + acol_f;
    }
    uint32_t a16_sts[4];
    #pragma unroll
    for (int j = 0; j < 4; j++) {
        uint32_t r = (uint32_t)(j * 32 + arow_c);
        uint32_t cb = (uint32_t)((tid & 15) * 8);
        a16_sts[j] = r * 128 + (cb ^ ((r & 7) << 4));
    }

    // B cp.async: 2 x 16B per thread per chunk
    int brow_g[2], bc16[2];
    uint32_t b_dst[2];
    #pragma unroll
    for (int j = 0; j < 2; j++) {
        int gid = tid + j * 512;
        brow_g[j] = gid >> 3;
        bc16[j] = gid & 7;
        b_dst[j] = (uint32_t)brow_g[j] * 128 +
                   (((uint32_t)(bc16[j] * 16)) ^ (((uint32_t)brow_g[j] & 7) << 4));
    }

    // ---- per-warp fragment mapping: 16 warps, warp tile 32x32 ----
    int wm = wid >> 2, wn = wid & 3;
    int lr = lane & 7, s1 = (lane >> 3) & 1, s2 = lane >> 4;
    uint32_t a_base[2], a_xor[2];
    #pragma unroll
    for (int mt = 0; mt < 2; mt++) {
        int arow = wm * 32 + mt * 16 + s1 * 8 + lr;
        a_base[mt] = (uint32_t)arow * 128;
        a_xor[mt] = ((uint32_t)arow & 7) << 4;
    }
    uint32_t b_base[2], b_xor[2];
    #pragma unroll
    for (int np = 0; np < 2; np++) {
        int brow = wn * 32 + np * 16 + s2 * 8 + lr;
        b_base[np] = (uint32_t)brow * 128;
        b_xor[np] = ((uint32_t)brow & 7) << 4;
    }
    uint32_t a_kadd = (uint32_t)(s2 * 16);
    uint32_t b_kadd = (uint32_t)(s1 * 16);

    float acc[2][4][4];
    #pragma unroll
    for (int mt = 0; mt < 2; mt++)
        #pragma unroll
        for (int nt = 0; nt < 4; nt++)
            #pragma unroll
            for (int e = 0; e < 4; e++) acc[mt][nt][e] = 0.f;

    // ---- prologue: groups g0..g3 ----
    #pragma unroll
    for (int c = 0; c < 3; c++) {
        uint32_t aB = sb + OFF_A32 + c * A32STG;
        uint32_t bB = sb + OFF_B + c * BSTG;
        int k0 = c * KCH;
        #pragma unroll
        for (int j = 0; j < 4; j++)
            CP_ASYNC16(aB + a32_off[j], a32_src[j] + k0);
        #pragma unroll
        for (int j = 0; j < 2; j++)
            CP_ASYNC16(bB + b_dst[j],
                       g_Wh + (size_t)brow_g[j] * Dsz + k0 + bc16[j] * 8);
        CP_COMMIT();
    }
    {
        uint32_t bB = sb + OFF_B + 3 * BSTG;
        #pragma unroll
        for (int j = 0; j < 2; j++)
            CP_ASYNC16(bB + b_dst[j],
                       g_Wh + (size_t)brow_g[j] * Dsz + 3 * KCH + bc16[j] * 8);
        CP_COMMIT();
    }

    int bs = 0;      // B ring stage of chunk c
    int bs4 = 4;     // B ring stage of chunk c+4
    int a3s = 0;     // A32 ring stage of chunk c
    for (int c = 0; c < NCHK; c++) {
        int p = c & 1;
        if (c <= 2)       { CP_WAIT3(); }
        else if (c <= 29) { CP_WAIT2(); }
        else if (c == 30) { CP_WAIT1(); }
        else              { CP_WAIT0(); }

        // LDS A32(c) -> convert -> STS A16 stage p
        {
            char* a32b = smem + OFF_A32 + a3s * A32STG;
            char* a16b = smem + p * A16STG;
            #pragma unroll
            for (int j = 0; j < 4; j++) {
                float4 v = *(const float4*)(a32b + a32_off[j]);
                uint32_t h01 = packh2(__float2half_rn(v.x), __float2half_rn(v.y));
                uint32_t h23 = packh2(__float2half_rn(v.z), __float2half_rn(v.w));
                *(uint2*)(a16b + a16_sts[j]) = make_uint2(h01, h23);
            }
        }
        __syncthreads();   // the ONLY barrier per chunk

        // issue group: A32(c+3) into ring stage a3s (just freed) + B(c+4)
        {
            bool hasA = (c + 3 < NCHK);
            bool hasB = (c + 4 < NCHK);
            if (hasA) {
                uint32_t aB = sb + OFF_A32 + a3s * A32STG;
                int k0 = (c + 3) * KCH;
                #pragma unroll
                for (int j = 0; j < 4; j++)
                    CP_ASYNC16(aB + a32_off[j], a32_src[j] + k0);
            }
            if (hasB) {
                uint32_t bB = sb + OFF_B + bs4 * BSTG;
                int k0 = (c + 4) * KCH;
                #pragma unroll
                for (int j = 0; j < 2; j++)
                    CP_ASYNC16(bB + b_dst[j],
                               g_Wh + (size_t)brow_g[j] * Dsz + k0 + bc16[j] * 8);
            }
            if (hasA || hasB) CP_COMMIT();
        }

        // compute on A16 stage p, B ring stage bs: 4 k16 steps
        {
            uint32_t Ahb = sb + p * A16STG;
            uint32_t Bb  = sb + OFF_B + bs * BSTG;
            #pragma unroll
            for (int ks = 0; ks < 4; ks++) {
                uint32_t ka = (uint32_t)(ks * 32) + a_kadd;
                uint32_t kb = (uint32_t)(ks * 32) + b_kadd;
                uint32_t af[2][4];
                #pragma unroll
                for (int mt = 0; mt < 2; mt++)
                    LDSM4(af[mt][0], af[mt][1], af[mt][2], af[mt][3],
                          Ahb + a_base[mt] + (ka ^ a_xor[mt]));
                uint32_t bf[4][2];
                #pragma unroll
                for (int np = 0; np < 2; np++)
                    LDSM4(bf[2 * np][0], bf[2 * np][1], bf[2 * np + 1][0], bf[2 * np + 1][1],
                          Bb + b_base[np] + (kb ^ b_xor[np]));
                #pragma unroll
                for (int mt = 0; mt < 2; mt++)
                    #pragma unroll
                    for (int nt = 0; nt < 4; nt++)
                        mma16816h(acc[mt][nt], af[mt], bf[nt]);
            }
        }

        bs  = (bs == 4)  ? 0 : bs + 1;
        bs4 = (bs4 == 4) ? 0 : bs4 + 1;
        a3s = (a3s == 2) ? 0 : a3s + 1;
    }
    __syncthreads();   // compute done; s_red overlays A32 ring below

    // ---- epilogue-constant load (post-mainloop) ----
    for (int i = tid; i < Tn * Hn; i += 512)
        ((float*)(smem + SM_CONTRIB))[i] = g_contrib[i];
    for (int i = tid; i < Bsz * Hn; i += 512)
        ((float*)(smem + SM_VW3))[i] = g_vw3[i];
    if (tid < Hn) {
        ((float*)(smem + SM_B1))[tid] = b1[tid];
        ((float*)(smem + SM_WOUT))[tid] = w_out[tid];
    }
    if (tid < Bsz * Tn)
        ((float*)(smem + SM_PROBS))[tid] = g_probs[tid];
    __syncthreads();

    // ----- Epilogue: base = acc + b1 + vw3[b]; 20-topic loop, 4/sync -----
    float* s_red   = (float*)(smem + SM_RED);          // [128][4][4]
    const float* s_vw3  = (const float*)(smem + SM_VW3);
    const float* s_b1v  = (const float*)(smem + SM_B1);
    const float* s_wo   = (const float*)(smem + SM_WOUT);
    const float* s_prob = (const float*)(smem + SM_PROBS);
    const float* s_con  = (const float*)(smem + SM_CONTRIB);
    float bo = b_out_p[0];
    int r = lane >> 2, q = lane & 3;

    #pragma unroll
    for (int mt = 0; mt < 2; mt++) {
        int rg0 = m0 + wm * 32 + mt * 16 + r;
        int rg1 = rg0 + 8;
        int b0 = rg0 / ROWS_PER_B;
        int b1i = rg1 / ROWS_PER_B;
        #pragma unroll
        for (int nt = 0; nt < 4; nt++)
            #pragma unroll
            for (int e = 0; e < 2; e++) {
                int col = wn * 32 + nt * 8 + 2 * q + e;
                acc[mt][nt][e]     += s_b1v[col] + s_vw3[b0 * Hn + col];
                acc[mt][nt][2 + e] += s_b1v[col] + s_vw3[b1i * Hn + col];
            }
    }

    float wv[4][2];
    #pragma unroll
    for (int nt = 0; nt < 4; nt++)
        #pragma unroll
        for (int e = 0; e < 2; e++)
            wv[nt][e] = s_wo[wn * 32 + nt * 8 + 2 * q + e];

    float orow = 0.f;     // per-row accumulator for threads tid<128
    int myrow = m0 + (tid & 127);
    int myb = myrow / ROWS_PER_B;

    for (int tg = 0; tg < 5; tg++) {
        #pragma unroll
        for (int mt = 0; mt < 2; mt++) {
            float p0[4] = {0.f, 0.f, 0.f, 0.f};
            float p1[4] = {0.f, 0.f, 0.f, 0.f};
            #pragma unroll
            for (int tt = 0; tt < 4; tt++) {
                int t = tg * 4 + tt;
                #pragma unroll
                for (int nt = 0; nt < 4; nt++)
                    #pragma unroll
                    for (int e = 0; e < 2; e++) {
                        float cv = s_con[t * Hn + wn * 32 + nt * 8 + 2 * q + e];
                        p0[tt] = fmaf(fmaxf(acc[mt][nt][e]     + cv, 0.f), wv[nt][e], p0[tt]);
                        p1[tt] = fmaf(fmaxf(acc[mt][nt][2 + e] + cv, 0.f), wv[nt][e], p1[tt]);
                    }
            }
            #pragma unroll
            for (int tt = 0; tt < 4; tt++) {
                p0[tt] += __shfl_xor_sync(0xffffffffu, p0[tt], 1);
                p0[tt] += __shfl_xor_sync(0xffffffffu, p0[tt], 2);
                p1[tt] += __shfl_xor_sync(0xffffffffu, p1[tt], 1);
                p1[tt] += __shfl_xor_sync(0xffffffffu, p1[tt], 2);
            }
            if (q == 0) {
                int row0 = wm * 32 + mt * 16 + r;
                #pragma unroll
                for (int tt = 0; tt < 4; tt++) {
                    s_red[(row0 * 4 + wn) * 4 + tt]       = p0[tt];
                    s_red[((row0 + 8) * 4 + wn) * 4 + tt] = p1[tt];
                }
            }
        }
        __syncthreads();
        if (tid < 128) {
            #pragma unroll
            for (int tt = 0; tt < 4; tt++) {
                int t = tg * 4 + tt;
                float s = s_red[(tid * 4 + 0) * 4 + tt] + s_red[(tid * 4 + 1) * 4 + tt]
                        + s_red[(tid * 4 + 2) * 4 + tt] + s_red[(tid * 4 + 3) * 4 + tt] + bo;
                float sig = 1.f / (1.f + __expf(-s));
                float sc = sig * s_prob[myb * Tn + t] - 0.01f;
                orow += fmaxf(sc, 0.f);
            }
        }
        __syncthreads();
    }

    if (tid < 128) {
        float v = orow * (1.f / (float)Tn);
        out[myrow] = v;
        if (out_size >= 2 * Mrows) out[Mrows + myrow] = v;
    }
}

// ---------------------------------------------------------------------------
extern "C" void kernel_launch(void* const* d_in, const int* in_sizes, int n_in,
                              void* d_out, int out_size) {
    const float* batch     = (const float*)d_in[0];
    const int*   seg_len   = (const int*)  d_in[1];
    const float* concept1  = (const float*)d_in[2];
    const float* concept2  = (const float*)d_in[3];
    const float* W_enc     = (const float*)d_in[4];
    const float* b_enc     = (const float*)d_in[5];
    const float* Wc1       = (const float*)d_in[6];
    const float* Wc2       = (const float*)d_in[7];
    const float* Wt1       = (const float*)d_in[8];
    const float* bt1       = (const float*)d_in[9];
    const float* Wt2       = (const float*)d_in[10];
    const float* bt2       = (const float*)d_in[11];
    const float* topic_emb = (const float*)d_in[12];
    const float* W1        = (const float*)d_in[13];
    const float* b1        = (const float*)d_in[14];
    const float* W2        = (const float*)d_in[15];
    const float* W3        = (const float*)d_in[16];
    const float* w_out     = (const float*)d_in[17];
    const float* b_out     = (const float*)d_in[18];
    float* out = (float*)d_out;

    cudaFuncSetAttribute(gemm_tc_kernel,
                         cudaFuncAttributeMaxDynamicSharedMemorySize, SM_BYTES);

    prep_kernel<<<Tn + 64 + 32 + 1, 256>>>(W1, topic_emb, W2);
    pool_kernel<<<dim3(Dsz / 256, Ssz, Bsz * 4), 256>>>(batch, seg_len);
    encsmall_kernel<<<dim3(Bsz, 5), 1024>>>(seg_len, concept1, concept2,
                                            W_enc, Wc1, Wc2, b_enc,
                                            Wt1, bt1, Wt2, bt2, W3);
    gemm_tc_kernel<<<Mrows / 128, 512, SM_BYTES>>>(batch, b1, w_out, b_out,
                                                   out, out_size);
}